// round 1
// baseline (speedup 1.0000x reference)
#include <cuda_runtime.h>
#include <math.h>

// Problem dims (fixed)
#define BB 4
#define SS 4096
#define DD 1024
#define AA 1024

// ---------------------------------------------------------------------------
// Device scratch (no allocations allowed in kernel_launch; __device__ globals
// are the sanctioned workaround).
// ---------------------------------------------------------------------------
__device__ float g_Q[(size_t)BB * SS * AA];              // 64 MB
__device__ float g_K[(size_t)BB * SS * AA];              // 64 MB
__device__ float g_V[(size_t)BB * SS * AA];              // 64 MB
__device__ float g_S[(size_t)BB * SS * SS];              // 256 MB scores

// ---------------------------------------------------------------------------
// Tiled SGEMM. C[M,N] = A[M,K] * B  (B is [K,N] if !TRANSB, [N,K] if TRANSB).
// All matrices row-major fp32. blockIdx.z batches via element strides.
// BM=BN=128, BK=16, TM=TN=8, 256 threads.
// ---------------------------------------------------------------------------
template <int BM, int BN, int BK, int TM, int TN, bool TRANSB>
__global__ __launch_bounds__(256)
void gemm_kernel(const float* __restrict__ A,
                 const float* __restrict__ B,
                 float* __restrict__ C,
                 int M, int N, int K,
                 long long sA, long long sB, long long sC)
{
    A += (long long)blockIdx.z * sA;
    B += (long long)blockIdx.z * sB;
    C += (long long)blockIdx.z * sC;

    __shared__ __align__(16) float As[BK][BM];
    __shared__ __align__(16) float Bs[BK][BN];

    const int tid = threadIdx.x;
    const int tx = tid % (BN / TN);   // 0..15
    const int ty = tid / (BN / TN);   // 0..15
    const int m0 = blockIdx.y * BM;
    const int n0 = blockIdx.x * BN;

    float acc[TM][TN];
#pragma unroll
    for (int i = 0; i < TM; i++)
#pragma unroll
        for (int j = 0; j < TN; j++) acc[i][j] = 0.0f;

    for (int kt = 0; kt < K; kt += BK) {
        // ---- load A tile (BM x BK), store transposed As[k][m] ----
#pragma unroll
        for (int i = tid; i < (BM * BK) / 4; i += 256) {
            int row = i / (BK / 4);
            int cv  = i % (BK / 4);
            float4 v = *(const float4*)(A + (long long)(m0 + row) * K + kt + cv * 4);
            As[cv * 4 + 0][row] = v.x;
            As[cv * 4 + 1][row] = v.y;
            As[cv * 4 + 2][row] = v.z;
            As[cv * 4 + 3][row] = v.w;
        }
        // ---- load B tile ----
        if (!TRANSB) {
            // B[K,N]: rows kt..kt+BK-1, cols n0..n0+BN-1
#pragma unroll
            for (int i = tid; i < (BK * BN) / 4; i += 256) {
                int row = i / (BN / 4);          // k
                int cv  = i % (BN / 4);          // n/4
                float4 v = *(const float4*)(B + (long long)(kt + row) * N + n0 + cv * 4);
                *(float4*)&Bs[row][cv * 4] = v;
            }
        } else {
            // B[N,K]: rows n0..n0+BN-1, cols kt..kt+BK-1, store Bs[k][n]
#pragma unroll
            for (int i = tid; i < (BN * BK) / 4; i += 256) {
                int row = i / (BK / 4);          // n
                int cv  = i % (BK / 4);          // k/4
                float4 v = *(const float4*)(B + (long long)(n0 + row) * K + kt + cv * 4);
                Bs[cv * 4 + 0][row] = v.x;
                Bs[cv * 4 + 1][row] = v.y;
                Bs[cv * 4 + 2][row] = v.z;
                Bs[cv * 4 + 3][row] = v.w;
            }
        }
        __syncthreads();

        // ---- compute ----
#pragma unroll
        for (int kk = 0; kk < BK; kk++) {
            float a[TM], b[TN];
            *(float4*)&a[0] = *(float4*)&As[kk][ty * TM];
            *(float4*)&a[4] = *(float4*)&As[kk][ty * TM + 4];
            *(float4*)&b[0] = *(float4*)&Bs[kk][tx * TN];
            *(float4*)&b[4] = *(float4*)&Bs[kk][tx * TN + 4];
#pragma unroll
            for (int i = 0; i < TM; i++)
#pragma unroll
                for (int j = 0; j < TN; j++)
                    acc[i][j] = fmaf(a[i], b[j], acc[i][j]);
        }
        __syncthreads();
    }

    // ---- epilogue ----
#pragma unroll
    for (int i = 0; i < TM; i++) {
        float* crow = C + (long long)(m0 + ty * TM + i) * N + n0 + tx * TN;
        *(float4*)crow       = *(float4*)&acc[i][0];
        *(float4*)(crow + 4) = *(float4*)&acc[i][4];
    }
}

// ---------------------------------------------------------------------------
// Row softmax, in place. One block (256 threads) per row of n=4096 floats.
// Scores have magnitude up to ~±500 (NO 1/sqrt(d) scaling) -> must subtract max.
// ---------------------------------------------------------------------------
__global__ __launch_bounds__(256)
void softmax_kernel(float* __restrict__ S, int n)
{
    const long long row = blockIdx.x;
    float* p = S + row * (long long)n;
    const int tid = threadIdx.x;

    // 4096 floats / 256 threads = 16 each = 4 float4
    float4 v[4];
    float m = -INFINITY;
#pragma unroll
    for (int i = 0; i < 4; i++) {
        v[i] = ((const float4*)p)[tid + i * 256];
        m = fmaxf(m, fmaxf(fmaxf(v[i].x, v[i].y), fmaxf(v[i].z, v[i].w)));
    }

    __shared__ float red[256];
    red[tid] = m;
    __syncthreads();
#pragma unroll
    for (int s = 128; s > 0; s >>= 1) {
        if (tid < s) red[tid] = fmaxf(red[tid], red[tid + s]);
        __syncthreads();
    }
    const float rowmax = red[0];
    __syncthreads();

    float sum = 0.0f;
#pragma unroll
    for (int i = 0; i < 4; i++) {
        v[i].x = __expf(v[i].x - rowmax);
        v[i].y = __expf(v[i].y - rowmax);
        v[i].z = __expf(v[i].z - rowmax);
        v[i].w = __expf(v[i].w - rowmax);
        sum += v[i].x + v[i].y + v[i].z + v[i].w;
    }

    red[tid] = sum;
    __syncthreads();
#pragma unroll
    for (int s = 128; s > 0; s >>= 1) {
        if (tid < s) red[tid] += red[tid + s];
        __syncthreads();
    }
    const float inv = 1.0f / red[0];
    __syncthreads();

#pragma unroll
    for (int i = 0; i < 4; i++) {
        v[i].x *= inv; v[i].y *= inv; v[i].z *= inv; v[i].w *= inv;
        ((float4*)p)[tid + i * 256] = v[i];
    }
}

// ---------------------------------------------------------------------------
// kernel_launch: proj (x3) -> QK^T -> softmax -> PV. Graph-capturable:
// plain kernel launches on the default stream, no sync, no allocation.
// ---------------------------------------------------------------------------
extern "C" void kernel_launch(void* const* d_in, const int* in_sizes, int n_in,
                              void* d_out, int out_size)
{
    const float* X  = (const float*)d_in[0];   // [B,S,D] -> [16384, 1024]
    const float* Wq = (const float*)d_in[1];   // [D,A]
    const float* Wk = (const float*)d_in[2];
    const float* Wv = (const float*)d_in[3];
    float* out = (float*)d_out;                // [B,S,A]

    float *Q, *K, *V, *Sc;
    cudaGetSymbolAddress((void**)&Q,  g_Q);
    cudaGetSymbolAddress((void**)&K,  g_K);
    cudaGetSymbolAddress((void**)&V,  g_V);
    cudaGetSymbolAddress((void**)&Sc, g_S);

    const dim3 blk(256);
    const int M = BB * SS;      // 16384

    // 1) Projections: [16384,1024] @ [1024,1024] (NN), one launch per weight.
    {
        dim3 grid(AA / 128, M / 128, 1);
        gemm_kernel<128,128,16,8,8,false><<<grid, blk>>>(X, Wq, Q, M, AA, DD, 0, 0, 0);
        gemm_kernel<128,128,16,8,8,false><<<grid, blk>>>(X, Wk, K, M, AA, DD, 0, 0, 0);
        gemm_kernel<128,128,16,8,8,false><<<grid, blk>>>(X, Wv, V, M, AA, DD, 0, 0, 0);
    }

    // 2) Scores: per batch, S = Q @ K^T  (NT), [4096,4096] k=1024
    {
        dim3 grid(SS / 128, SS / 128, BB);
        gemm_kernel<128,128,16,8,8,true><<<grid, blk>>>(
            Q, K, Sc, SS, SS, AA,
            (long long)SS * AA, (long long)SS * AA, (long long)SS * SS);
    }

    // 3) Softmax over rows of S (16384 rows of 4096)
    softmax_kernel<<<BB * SS, blk>>>(Sc, SS);

    // 4) Output: per batch, O = P @ V (NN), [4096,1024] k=4096
    {
        dim3 grid(AA / 128, SS / 128, BB);
        gemm_kernel<128,128,16,8,8,false><<<grid, blk>>>(
            Sc, V, out, SS, AA, SS,
            (long long)SS * SS, (long long)SS * AA, (long long)SS * AA);
    }
}

// round 3
// speedup vs baseline: 2.1628x; 2.1628x over previous
#include <cuda_runtime.h>
#include <cuda_bf16.h>
#include <cstdint>
#include <math.h>

// Problem dims (fixed)
#define BB 4
#define SS 4096
#define DD 1024
#define AA 1024
#define MTOT (BB*SS)   // 16384

// ---------------------------------------------------------------------------
// Device scratch (allocation-free rule: __device__ globals)
// ---------------------------------------------------------------------------
__device__ float g_Qf[(size_t)MTOT * AA];                 // 64 MB
__device__ float g_Kf[(size_t)MTOT * AA];                 // 64 MB
__device__ float g_Vf[(size_t)MTOT * AA];                 // 64 MB
__device__ float g_S [(size_t)BB * SS * SS];              // 256 MB scores
__device__ __nv_bfloat16 g_Xhi[(size_t)MTOT * DD];
__device__ __nv_bfloat16 g_Xlo[(size_t)MTOT * DD];
__device__ __nv_bfloat16 g_Wh[3][(size_t)AA * DD];        // W^T splits [A,D]
__device__ __nv_bfloat16 g_Wl[3][(size_t)AA * DD];
__device__ __nv_bfloat16 g_Qhi[(size_t)MTOT * AA];
__device__ __nv_bfloat16 g_Qlo[(size_t)MTOT * AA];
__device__ __nv_bfloat16 g_Khi[(size_t)MTOT * AA];
__device__ __nv_bfloat16 g_Klo[(size_t)MTOT * AA];
__device__ __nv_bfloat16 g_Vthi[(size_t)BB * AA * SS];    // V^T per batch [A,S]
__device__ __nv_bfloat16 g_Vtlo[(size_t)BB * AA * SS];
__device__ __nv_bfloat16 g_Phi[(size_t)BB * SS * SS];     // 128 MB
__device__ __nv_bfloat16 g_Plo[(size_t)BB * SS * SS];     // 128 MB

// ---------------------------------------------------------------------------
// Helpers
// ---------------------------------------------------------------------------
__device__ __forceinline__ uint32_t smem_u32(const void* p) {
    uint32_t a;
    asm("{ .reg .u64 t; cvta.to.shared.u64 t, %1; cvt.u32.u64 %0, t; }" : "=r"(a) : "l"(p));
    return a;
}

#define CP_ASYNC16(saddr, gaddr) \
    asm volatile("cp.async.cg.shared.global [%0], [%1], 16;" :: "r"(saddr), "l"(gaddr))
#define CP_COMMIT()  asm volatile("cp.async.commit_group;" ::: "memory")
#define CP_WAIT1()   asm volatile("cp.async.wait_group 1;" ::: "memory")
#define CP_WAIT0()   asm volatile("cp.async.wait_group 0;" ::: "memory")

#define MMA_BF16(c, a, b) \
    asm volatile("mma.sync.aligned.m16n8k16.row.col.f32.bf16.bf16.f32 " \
        "{%0,%1,%2,%3}, {%4,%5,%6,%7}, {%8,%9}, {%0,%1,%2,%3};" \
        : "+f"((c)[0]), "+f"((c)[1]), "+f"((c)[2]), "+f"((c)[3]) \
        : "r"((a)[0]), "r"((a)[1]), "r"((a)[2]), "r"((a)[3]), \
          "r"((b)[0]), "r"((b)[1]))

// ---------------------------------------------------------------------------
// HMMA GEMM with bf16 hi/lo 4-term split.
// C[M,N](fp32) = (Ahi+Alo)[M,K] * (Bhi+Blo)[N,K]^T, all bf16 K-major.
// CTA tile 128x128, K chunk 64, 2-stage cp.async double buffer.
// 8 warps: 4 (m) x 2 (n); warp tile 32x64 -> 2 m16 x 8 n8 mma tiles.
// ---------------------------------------------------------------------------
#define KC       64
#define ROWB     144                         // 64 bf16 + 8 pad = 72 el = 144 B
#define TILE_B   (128 * ROWB)                // 18432 B
#define STAGE_B  (4 * TILE_B)                // Ahi, Alo, Bhi, Blo
#define SMEM_DYN (2 * STAGE_B)               // 147456 B

__device__ __forceinline__ void load_tile_async(const __nv_bfloat16* __restrict__ g,
                                                int ldK, char* sb, int tid)
{
    // 128 rows x 64 bf16 = 1024 chunks of 16B; 4 per thread
#pragma unroll
    for (int i = 0; i < 4; i++) {
        int ch = tid + i * 256;
        int row = ch >> 3, c = ch & 7;
        uint32_t sa = smem_u32(sb + row * ROWB + c * 16);
        CP_ASYNC16(sa, g + (size_t)row * ldK + c * 8);
    }
}

__global__ __launch_bounds__(256, 1)
void gemm_mma(const __nv_bfloat16* __restrict__ Ahi, const __nv_bfloat16* __restrict__ Alo,
              const __nv_bfloat16* __restrict__ Bhi, const __nv_bfloat16* __restrict__ Blo,
              float* __restrict__ C,
              int K, int ldC,
              long long sA, long long sB, long long sC)
{
    extern __shared__ __align__(128) char smem[];
    const int tid = threadIdx.x;
    const int wid = tid >> 5, lane = tid & 31;
    const int wm = wid & 3, wn = wid >> 2;
    const int m0 = blockIdx.y * 128;
    const int n0 = blockIdx.x * 128;

    const __nv_bfloat16* pAh = Ahi + (size_t)blockIdx.z * sA + (size_t)m0 * K;
    const __nv_bfloat16* pAl = Alo + (size_t)blockIdx.z * sA + (size_t)m0 * K;
    const __nv_bfloat16* pBh = Bhi + (size_t)blockIdx.z * sB + (size_t)n0 * K;
    const __nv_bfloat16* pBl = Blo + (size_t)blockIdx.z * sB + (size_t)n0 * K;

    float acc[2][8][4];
#pragma unroll
    for (int mt = 0; mt < 2; mt++)
#pragma unroll
        for (int nt = 0; nt < 8; nt++)
#pragma unroll
            for (int j = 0; j < 4; j++) acc[mt][nt][j] = 0.0f;

    const int nch = K >> 6;

    // prologue: stages 0 and 1
    {
        char* sp = smem;
        load_tile_async(pAh, K, sp,              tid);
        load_tile_async(pAl, K, sp +   TILE_B,   tid);
        load_tile_async(pBh, K, sp + 2*TILE_B,   tid);
        load_tile_async(pBl, K, sp + 3*TILE_B,   tid);
        CP_COMMIT();
        sp = smem + STAGE_B;
        load_tile_async(pAh + KC, K, sp,              tid);
        load_tile_async(pAl + KC, K, sp +   TILE_B,   tid);
        load_tile_async(pBh + KC, K, sp + 2*TILE_B,   tid);
        load_tile_async(pBl + KC, K, sp + 3*TILE_B,   tid);
        CP_COMMIT();
    }

    const int r  = lane >> 2;        // 0..7
    const int kq = lane & 3;         // 0..3  (k-pair index)

    for (int c = 0; c < nch; ++c) {
        if (c + 1 < nch) CP_WAIT1(); else CP_WAIT0();
        __syncthreads();

        const char* sp  = smem + (c & 1) * STAGE_B;
        const char* sAh = sp;
        const char* sAl = sp +     TILE_B;
        const char* sBh = sp + 2 * TILE_B;
        const char* sBl = sp + 3 * TILE_B;

#pragma unroll
        for (int ks = 0; ks < 4; ++ks) {
            const int kb = (ks * 8 + kq) * 4;        // byte offset of k-pair word

            uint32_t ah[2][4], al[2][4];
#pragma unroll
            for (int mt = 0; mt < 2; mt++) {
                const int row = wm * 32 + mt * 16 + r;
                const char* a0 = sAh + row * ROWB + kb;
                const char* a1 = sAh + (row + 8) * ROWB + kb;
                ah[mt][0] = *(const uint32_t*)(a0);
                ah[mt][1] = *(const uint32_t*)(a1);
                ah[mt][2] = *(const uint32_t*)(a0 + 16);
                ah[mt][3] = *(const uint32_t*)(a1 + 16);
                const char* b0 = sAl + row * ROWB + kb;
                const char* b1 = sAl + (row + 8) * ROWB + kb;
                al[mt][0] = *(const uint32_t*)(b0);
                al[mt][1] = *(const uint32_t*)(b1);
                al[mt][2] = *(const uint32_t*)(b0 + 16);
                al[mt][3] = *(const uint32_t*)(b1 + 16);
            }
            uint32_t bh[8][2], bl[8][2];
#pragma unroll
            for (int nt = 0; nt < 8; nt++) {
                const int n = wn * 64 + nt * 8 + r;
                const char* p = sBh + n * ROWB + kb;
                bh[nt][0] = *(const uint32_t*)(p);
                bh[nt][1] = *(const uint32_t*)(p + 16);
                const char* q = sBl + n * ROWB + kb;
                bl[nt][0] = *(const uint32_t*)(q);
                bl[nt][1] = *(const uint32_t*)(q + 16);
            }
#pragma unroll
            for (int mt = 0; mt < 2; mt++)
#pragma unroll
                for (int nt = 0; nt < 8; nt++) {
                    MMA_BF16(acc[mt][nt], ah[mt], bh[nt]);
                    MMA_BF16(acc[mt][nt], ah[mt], bl[nt]);
                    MMA_BF16(acc[mt][nt], al[mt], bh[nt]);
                    MMA_BF16(acc[mt][nt], al[mt], bl[nt]);
                }
        }

        if (c + 2 < nch) {
            __syncthreads();   // everyone done reading buffer (c&1) before refill
            char* dp = smem + (c & 1) * STAGE_B;
            const int k0 = (c + 2) * KC;
            load_tile_async(pAh + k0, K, dp,              tid);
            load_tile_async(pAl + k0, K, dp +   TILE_B,   tid);
            load_tile_async(pBh + k0, K, dp + 2*TILE_B,   tid);
            load_tile_async(pBl + k0, K, dp + 3*TILE_B,   tid);
            CP_COMMIT();
        }
    }

    // epilogue
    float* Cw = C + (size_t)blockIdx.z * sC
                  + (size_t)(m0 + wm * 32) * ldC + n0 + wn * 64;
    const int cq = (lane & 3) * 2;
#pragma unroll
    for (int mt = 0; mt < 2; mt++)
#pragma unroll
        for (int nt = 0; nt < 8; nt++) {
            float* p0 = Cw + (size_t)(mt * 16 + r) * ldC + nt * 8 + cq;
            float* p1 = p0 + 8 * (size_t)ldC;
            *(float2*)p0 = make_float2(acc[mt][nt][0], acc[mt][nt][1]);
            *(float2*)p1 = make_float2(acc[mt][nt][2], acc[mt][nt][3]);
        }
}

// ---------------------------------------------------------------------------
// fp32 -> bf16 hi/lo split (elementwise)
// ---------------------------------------------------------------------------
__global__ __launch_bounds__(256)
void split_plain(const float* __restrict__ in, __nv_bfloat16* __restrict__ hi,
                 __nv_bfloat16* __restrict__ lo, size_t n)
{
    size_t i = ((size_t)blockIdx.x * 256 + threadIdx.x) * 4;
    if (i >= n) return;
    float4 x = *(const float4*)(in + i);
    __nv_bfloat16 h0 = __float2bfloat16_rn(x.x), h1 = __float2bfloat16_rn(x.y);
    __nv_bfloat16 h2 = __float2bfloat16_rn(x.z), h3 = __float2bfloat16_rn(x.w);
    __nv_bfloat16 l0 = __float2bfloat16_rn(x.x - __bfloat162float(h0));
    __nv_bfloat16 l1 = __float2bfloat16_rn(x.y - __bfloat162float(h1));
    __nv_bfloat16 l2 = __float2bfloat16_rn(x.z - __bfloat162float(h2));
    __nv_bfloat16 l3 = __float2bfloat16_rn(x.w - __bfloat162float(h3));
    *(__nv_bfloat162*)(hi + i)     = __nv_bfloat162(h0, h1);
    *(__nv_bfloat162*)(hi + i + 2) = __nv_bfloat162(h2, h3);
    *(__nv_bfloat162*)(lo + i)     = __nv_bfloat162(l0, l1);
    *(__nv_bfloat162*)(lo + i + 2) = __nv_bfloat162(l2, l3);
}

// ---------------------------------------------------------------------------
// fp32 [R,C] -> transposed bf16 hi/lo [C,R] (batched via z)
// ---------------------------------------------------------------------------
__global__ __launch_bounds__(256)
void transpose_split(const float* __restrict__ in, __nv_bfloat16* __restrict__ hiT,
                     __nv_bfloat16* __restrict__ loT, int R, int C,
                     long long sIn, long long sOut)
{
    __shared__ float t[32][33];
    in  += (size_t)blockIdx.z * sIn;
    hiT += (size_t)blockIdx.z * sOut;
    loT += (size_t)blockIdx.z * sOut;
    const int r0 = blockIdx.y * 32, c0 = blockIdx.x * 32;
    const int tx = threadIdx.x & 31, ty = threadIdx.x >> 5;
#pragma unroll
    for (int i = ty; i < 32; i += 8)
        t[i][tx] = in[(size_t)(r0 + i) * C + c0 + tx];
    __syncthreads();
#pragma unroll
    for (int i = ty; i < 32; i += 8) {
        float x = t[tx][i];
        __nv_bfloat16 h = __float2bfloat16_rn(x);
        __nv_bfloat16 l = __float2bfloat16_rn(x - __bfloat162float(h));
        size_t o = (size_t)(c0 + i) * R + r0 + tx;
        hiT[o] = h; loT[o] = l;
    }
}

// ---------------------------------------------------------------------------
// Row softmax (4096 cols) fused with bf16 hi/lo split of the weights
// ---------------------------------------------------------------------------
__global__ __launch_bounds__(256)
void softmax_split(const float* __restrict__ S, __nv_bfloat16* __restrict__ Ph,
                   __nv_bfloat16* __restrict__ Pl)
{
    const size_t row = blockIdx.x;
    const float* p = S + row * (size_t)SS;
    const int tid = threadIdx.x;

    float4 v[4];
    float m = -INFINITY;
#pragma unroll
    for (int i = 0; i < 4; i++) {
        v[i] = ((const float4*)p)[tid + i * 256];
        m = fmaxf(m, fmaxf(fmaxf(v[i].x, v[i].y), fmaxf(v[i].z, v[i].w)));
    }
    __shared__ float red[256];
    red[tid] = m; __syncthreads();
#pragma unroll
    for (int s = 128; s > 0; s >>= 1) {
        if (tid < s) red[tid] = fmaxf(red[tid], red[tid + s]);
        __syncthreads();
    }
    const float rowmax = red[0];
    __syncthreads();

    float sum = 0.0f;
#pragma unroll
    for (int i = 0; i < 4; i++) {
        v[i].x = __expf(v[i].x - rowmax);
        v[i].y = __expf(v[i].y - rowmax);
        v[i].z = __expf(v[i].z - rowmax);
        v[i].w = __expf(v[i].w - rowmax);
        sum += v[i].x + v[i].y + v[i].z + v[i].w;
    }
    red[tid] = sum; __syncthreads();
#pragma unroll
    for (int s = 128; s > 0; s >>= 1) {
        if (tid < s) red[tid] += red[tid + s];
        __syncthreads();
    }
    const float inv = 1.0f / red[0];
    __syncthreads();

#pragma unroll
    for (int i = 0; i < 4; i++) {
        float f0 = v[i].x * inv, f1 = v[i].y * inv, f2 = v[i].z * inv, f3 = v[i].w * inv;
        __nv_bfloat16 h0 = __float2bfloat16_rn(f0), h1 = __float2bfloat16_rn(f1);
        __nv_bfloat16 h2 = __float2bfloat16_rn(f2), h3 = __float2bfloat16_rn(f3);
        __nv_bfloat16 l0 = __float2bfloat16_rn(f0 - __bfloat162float(h0));
        __nv_bfloat16 l1 = __float2bfloat16_rn(f1 - __bfloat162float(h1));
        __nv_bfloat16 l2 = __float2bfloat16_rn(f2 - __bfloat162float(h2));
        __nv_bfloat16 l3 = __float2bfloat16_rn(f3 - __bfloat162float(h3));
        size_t o = row * (size_t)SS + (size_t)(tid + i * 256) * 4;
        *(__nv_bfloat162*)(Ph + o)     = __nv_bfloat162(h0, h1);
        *(__nv_bfloat162*)(Ph + o + 2) = __nv_bfloat162(h2, h3);
        *(__nv_bfloat162*)(Pl + o)     = __nv_bfloat162(l0, l1);
        *(__nv_bfloat162*)(Pl + o + 2) = __nv_bfloat162(l2, l3);
    }
}

// ---------------------------------------------------------------------------
// kernel_launch — graph-capturable pipeline
// ---------------------------------------------------------------------------
extern "C" void kernel_launch(void* const* d_in, const int* in_sizes, int n_in,
                              void* d_out, int out_size)
{
    const float* X  = (const float*)d_in[0];
    const float* Wq = (const float*)d_in[1];
    const float* Wk = (const float*)d_in[2];
    const float* Wv = (const float*)d_in[3];
    float* out = (float*)d_out;

    float *Qf, *Kf, *Vf, *Sc;
    __nv_bfloat16 *Xhi, *Xlo, *Wh, *Wl, *Qhi, *Qlo, *Khi, *Klo, *Vthi, *Vtlo, *Phi, *Plo;
    cudaGetSymbolAddress((void**)&Qf, g_Qf);
    cudaGetSymbolAddress((void**)&Kf, g_Kf);
    cudaGetSymbolAddress((void**)&Vf, g_Vf);
    cudaGetSymbolAddress((void**)&Sc, g_S);
    cudaGetSymbolAddress((void**)&Xhi, g_Xhi);
    cudaGetSymbolAddress((void**)&Xlo, g_Xlo);
    cudaGetSymbolAddress((void**)&Wh, g_Wh);
    cudaGetSymbolAddress((void**)&Wl, g_Wl);
    cudaGetSymbolAddress((void**)&Qhi, g_Qhi);
    cudaGetSymbolAddress((void**)&Qlo, g_Qlo);
    cudaGetSymbolAddress((void**)&Khi, g_Khi);
    cudaGetSymbolAddress((void**)&Klo, g_Klo);
    cudaGetSymbolAddress((void**)&Vthi, g_Vthi);
    cudaGetSymbolAddress((void**)&Vtlo, g_Vtlo);
    cudaGetSymbolAddress((void**)&Phi, g_Phi);
    cudaGetSymbolAddress((void**)&Plo, g_Plo);

    cudaFuncSetAttribute(gemm_mma, cudaFuncAttributeMaxDynamicSharedMemorySize, SMEM_DYN);

    const size_t WSZ = (size_t)AA * DD;

    // 1) split X; transpose+split the three weight matrices to [A,D]
    split_plain<<<(MTOT * (size_t)DD) / 1024, 256>>>(X, Xhi, Xlo, (size_t)MTOT * DD);
    {
        dim3 g(AA / 32, DD / 32, 1);
        transpose_split<<<g, 256>>>(Wq, Wh + 0 * WSZ, Wl + 0 * WSZ, DD, AA, 0, 0);
        transpose_split<<<g, 256>>>(Wk, Wh + 1 * WSZ, Wl + 1 * WSZ, DD, AA, 0, 0);
        transpose_split<<<g, 256>>>(Wv, Wh + 2 * WSZ, Wl + 2 * WSZ, DD, AA, 0, 0);
    }

    // 2) projections: Q/K/V = X @ W  -> fp32
    {
        dim3 g(AA / 128, MTOT / 128, 1);
        gemm_mma<<<g, 256, SMEM_DYN>>>(Xhi, Xlo, Wh + 0*WSZ, Wl + 0*WSZ, Qf, DD, AA, 0, 0, 0);
        gemm_mma<<<g, 256, SMEM_DYN>>>(Xhi, Xlo, Wh + 1*WSZ, Wl + 1*WSZ, Kf, DD, AA, 0, 0, 0);
        gemm_mma<<<g, 256, SMEM_DYN>>>(Xhi, Xlo, Wh + 2*WSZ, Wl + 2*WSZ, Vf, DD, AA, 0, 0, 0);
    }

    // 3) split Q,K; transpose+split V per batch to [A,S]
    split_plain<<<(MTOT * (size_t)AA) / 1024, 256>>>(Qf, Qhi, Qlo, (size_t)MTOT * AA);
    split_plain<<<(MTOT * (size_t)AA) / 1024, 256>>>(Kf, Khi, Klo, (size_t)MTOT * AA);
    {
        dim3 g(AA / 32, SS / 32, BB);
        transpose_split<<<g, 256>>>(Vf, Vthi, Vtlo, SS, AA,
                                    (long long)SS * AA, (long long)SS * AA);
    }

    // 4) scores: S = Q @ K^T per batch
    {
        dim3 g(SS / 128, SS / 128, BB);
        gemm_mma<<<g, 256, SMEM_DYN>>>(Qhi, Qlo, Khi, Klo, Sc, AA, SS,
                                       (long long)SS * AA, (long long)SS * AA,
                                       (long long)SS * SS);
    }

    // 5) softmax + split to bf16 hi/lo
    softmax_split<<<BB * SS, 256>>>(Sc, Phi, Plo);

    // 6) output: O = P @ V per batch (V^T is K-major)
    {
        dim3 g(AA / 128, SS / 128, BB);
        gemm_mma<<<g, 256, SMEM_DYN>>>(Phi, Plo, Vthi, Vtlo, out, SS, AA,
                                       (long long)SS * SS, (long long)AA * SS,
                                       (long long)SS * AA);
    }
}

// round 4
// speedup vs baseline: 2.5904x; 1.1977x over previous
#include <cuda_runtime.h>
#include <cuda_bf16.h>
#include <cstdint>
#include <math.h>

// Problem dims (fixed)
#define BB 4
#define SS 4096
#define DD 1024
#define AA 1024
#define MTOT (BB*SS)   // 16384

// ---------------------------------------------------------------------------
// Device scratch
// ---------------------------------------------------------------------------
__device__ float g_Vf[(size_t)MTOT * AA];                 // 64 MB
__device__ float g_S [(size_t)BB * SS * SS];              // 256 MB scores
__device__ __nv_bfloat16 g_Xhi[(size_t)MTOT * DD];
__device__ __nv_bfloat16 g_Xlo[(size_t)MTOT * DD];
__device__ __nv_bfloat16 g_Wh[3][(size_t)AA * DD];        // W^T splits [A,D]
__device__ __nv_bfloat16 g_Wl[3][(size_t)AA * DD];
__device__ __nv_bfloat16 g_Qhi[(size_t)MTOT * AA];
__device__ __nv_bfloat16 g_Qlo[(size_t)MTOT * AA];
__device__ __nv_bfloat16 g_Khi[(size_t)MTOT * AA];
__device__ __nv_bfloat16 g_Klo[(size_t)MTOT * AA];
__device__ __nv_bfloat16 g_Vthi[(size_t)BB * AA * SS];    // V^T per batch [A,S]
__device__ __nv_bfloat16 g_Vtlo[(size_t)BB * AA * SS];
__device__ __nv_bfloat16 g_Phi[(size_t)BB * SS * SS];     // 128 MB
__device__ __nv_bfloat16 g_Plo[(size_t)BB * SS * SS];     // 128 MB

// ---------------------------------------------------------------------------
// Helpers
// ---------------------------------------------------------------------------
__device__ __forceinline__ uint32_t smem_u32(const void* p) {
    uint32_t a;
    asm("{ .reg .u64 t; cvta.to.shared.u64 t, %1; cvt.u32.u64 %0, t; }" : "=r"(a) : "l"(p));
    return a;
}

#define CP_ASYNC16(saddr, gaddr) \
    asm volatile("cp.async.cg.shared.global [%0], [%1], 16;" :: "r"(saddr), "l"(gaddr))
#define CP_COMMIT()  asm volatile("cp.async.commit_group;" ::: "memory")
#define CP_WAIT1()   asm volatile("cp.async.wait_group 1;" ::: "memory")
#define CP_WAIT0()   asm volatile("cp.async.wait_group 0;" ::: "memory")

#define MMA_BF16(c, a, b) \
    asm volatile("mma.sync.aligned.m16n8k16.row.col.f32.bf16.bf16.f32 " \
        "{%0,%1,%2,%3}, {%4,%5,%6,%7}, {%8,%9}, {%0,%1,%2,%3};" \
        : "+f"((c)[0]), "+f"((c)[1]), "+f"((c)[2]), "+f"((c)[3]) \
        : "r"((a)[0]), "r"((a)[1]), "r"((a)[2]), "r"((a)[3]), \
          "r"((b)[0]), "r"((b)[1]))

// ---------------------------------------------------------------------------
// HMMA GEMM with bf16 hi/lo 3-term split (hh + hl + lh; lo*lo dropped).
// C[M,N](fp32 or bf16 hi/lo) = (Ahi+Alo)[M,K] * (Bhi+Blo)[N,K]^T, K-major.
// CTA tile 128x128, K chunk 64, 3-stage cp.async pipeline (one sync/chunk).
// 8 warps: 4 (m) x 2 (n); warp tile 32x64 -> 2 m16 x 8 n8 mma tiles.
// ---------------------------------------------------------------------------
#define KC       64
#define ROWB     144                         // 64 bf16 + 8 pad = 72 el = 144 B
#define TILE_B   (128 * ROWB)                // 18432 B
#define STAGE_B  (4 * TILE_B)                // Ahi, Alo, Bhi, Blo = 73728 B
#define SMEM_DYN (3 * STAGE_B)               // 221184 B

__device__ __forceinline__ void load_tile_async(const __nv_bfloat16* __restrict__ g,
                                                int ldK, char* sb, int tid)
{
#pragma unroll
    for (int i = 0; i < 4; i++) {
        int ch = tid + i * 256;
        int row = ch >> 3, c = ch & 7;
        uint32_t sa = smem_u32(sb + row * ROWB + c * 16);
        CP_ASYNC16(sa, g + (size_t)row * ldK + c * 8);
    }
}

__device__ __forceinline__ void load_stage(const __nv_bfloat16* pAh, const __nv_bfloat16* pAl,
                                           const __nv_bfloat16* pBh, const __nv_bfloat16* pBl,
                                           int k0, int K, char* sp, int tid)
{
    load_tile_async(pAh + k0, K, sp,              tid);
    load_tile_async(pAl + k0, K, sp +   TILE_B,   tid);
    load_tile_async(pBh + k0, K, sp + 2*TILE_B,   tid);
    load_tile_async(pBl + k0, K, sp + 3*TILE_B,   tid);
    CP_COMMIT();
}

template <bool SPLIT_OUT>
__global__ __launch_bounds__(256, 1)
void gemm_mma(const __nv_bfloat16* __restrict__ Ahi, const __nv_bfloat16* __restrict__ Alo,
              const __nv_bfloat16* __restrict__ Bhi, const __nv_bfloat16* __restrict__ Blo,
              float* __restrict__ C,
              __nv_bfloat16* __restrict__ Chi, __nv_bfloat16* __restrict__ Clo,
              int K, int ldC,
              long long sA, long long sB, long long sC)
{
    extern __shared__ __align__(128) char smem[];
    const int tid = threadIdx.x;
    const int wid = tid >> 5, lane = tid & 31;
    const int wm = wid & 3, wn = wid >> 2;
    const int m0 = blockIdx.y * 128;
    const int n0 = blockIdx.x * 128;

    const __nv_bfloat16* pAh = Ahi + (size_t)blockIdx.z * sA + (size_t)m0 * K;
    const __nv_bfloat16* pAl = Alo + (size_t)blockIdx.z * sA + (size_t)m0 * K;
    const __nv_bfloat16* pBh = Bhi + (size_t)blockIdx.z * sB + (size_t)n0 * K;
    const __nv_bfloat16* pBl = Blo + (size_t)blockIdx.z * sB + (size_t)n0 * K;

    float acc[2][8][4];
#pragma unroll
    for (int mt = 0; mt < 2; mt++)
#pragma unroll
        for (int nt = 0; nt < 8; nt++)
#pragma unroll
            for (int j = 0; j < 4; j++) acc[mt][nt][j] = 0.0f;

    const int nch = K >> 6;

    // prologue: chunks 0 and 1 into stages 0 and 1
    load_stage(pAh, pAl, pBh, pBl, 0,  K, smem,           tid);
    load_stage(pAh, pAl, pBh, pBl, KC, K, smem + STAGE_B, tid);

    const int r  = lane >> 2;        // 0..7
    const int kq = lane & 3;         // 0..3  (k-pair index)

    for (int c = 0; c < nch; ++c) {
        if (c + 1 < nch) CP_WAIT1(); else CP_WAIT0();
        __syncthreads();

        // refill stage (c+2)%3 (it was consumed at iter c-1; sync above protects it)
        if (c + 2 < nch)
            load_stage(pAh, pAl, pBh, pBl, (c + 2) * KC, K,
                       smem + ((c + 2) % 3) * STAGE_B, tid);

        const char* sp  = smem + (c % 3) * STAGE_B;
        const char* sAh = sp;
        const char* sAl = sp +     TILE_B;
        const char* sBh = sp + 2 * TILE_B;
        const char* sBl = sp + 3 * TILE_B;

#pragma unroll
        for (int ks = 0; ks < 4; ++ks) {
            const int kb = (ks * 8 + kq) * 4;        // byte offset of k-pair word

            uint32_t ah[2][4], al[2][4];
#pragma unroll
            for (int mt = 0; mt < 2; mt++) {
                const int row = wm * 32 + mt * 16 + r;
                const char* a0 = sAh + row * ROWB + kb;
                const char* a1 = sAh + (row + 8) * ROWB + kb;
                ah[mt][0] = *(const uint32_t*)(a0);
                ah[mt][1] = *(const uint32_t*)(a1);
                ah[mt][2] = *(const uint32_t*)(a0 + 16);
                ah[mt][3] = *(const uint32_t*)(a1 + 16);
                const char* b0 = sAl + row * ROWB + kb;
                const char* b1 = sAl + (row + 8) * ROWB + kb;
                al[mt][0] = *(const uint32_t*)(b0);
                al[mt][1] = *(const uint32_t*)(b1);
                al[mt][2] = *(const uint32_t*)(b0 + 16);
                al[mt][3] = *(const uint32_t*)(b1 + 16);
            }
            uint32_t bh[8][2], bl[8][2];
#pragma unroll
            for (int nt = 0; nt < 8; nt++) {
                const int n = wn * 64 + nt * 8 + r;
                const char* p = sBh + n * ROWB + kb;
                bh[nt][0] = *(const uint32_t*)(p);
                bh[nt][1] = *(const uint32_t*)(p + 16);
                const char* q = sBl + n * ROWB + kb;
                bl[nt][0] = *(const uint32_t*)(q);
                bl[nt][1] = *(const uint32_t*)(q + 16);
            }
#pragma unroll
            for (int mt = 0; mt < 2; mt++)
#pragma unroll
                for (int nt = 0; nt < 8; nt++) {
                    MMA_BF16(acc[mt][nt], ah[mt], bh[nt]);
                    MMA_BF16(acc[mt][nt], ah[mt], bl[nt]);
                    MMA_BF16(acc[mt][nt], al[mt], bh[nt]);
                }
        }
    }

    // epilogue
    const int cq = (lane & 3) * 2;
    if (!SPLIT_OUT) {
        float* Cw = C + (size_t)blockIdx.z * sC
                      + (size_t)(m0 + wm * 32) * ldC + n0 + wn * 64;
#pragma unroll
        for (int mt = 0; mt < 2; mt++)
#pragma unroll
            for (int nt = 0; nt < 8; nt++) {
                float* p0 = Cw + (size_t)(mt * 16 + r) * ldC + nt * 8 + cq;
                float* p1 = p0 + 8 * (size_t)ldC;
                *(float2*)p0 = make_float2(acc[mt][nt][0], acc[mt][nt][1]);
                *(float2*)p1 = make_float2(acc[mt][nt][2], acc[mt][nt][3]);
            }
    } else {
        const size_t off = (size_t)blockIdx.z * sC
                         + (size_t)(m0 + wm * 32) * ldC + n0 + wn * 64;
        __nv_bfloat16* Hw = Chi + off;
        __nv_bfloat16* Lw = Clo + off;
#pragma unroll
        for (int mt = 0; mt < 2; mt++)
#pragma unroll
            for (int nt = 0; nt < 8; nt++) {
                const size_t o0 = (size_t)(mt * 16 + r) * ldC + nt * 8 + cq;
                const size_t o1 = o0 + 8 * (size_t)ldC;
                float x0 = acc[mt][nt][0], x1 = acc[mt][nt][1];
                float x2 = acc[mt][nt][2], x3 = acc[mt][nt][3];
                __nv_bfloat16 h0 = __float2bfloat16_rn(x0), h1 = __float2bfloat16_rn(x1);
                __nv_bfloat16 h2 = __float2bfloat16_rn(x2), h3 = __float2bfloat16_rn(x3);
                *(__nv_bfloat162*)(Hw + o0) = __nv_bfloat162(h0, h1);
                *(__nv_bfloat162*)(Hw + o1) = __nv_bfloat162(h2, h3);
                __nv_bfloat16 l0 = __float2bfloat16_rn(x0 - __bfloat162float(h0));
                __nv_bfloat16 l1 = __float2bfloat16_rn(x1 - __bfloat162float(h1));
                __nv_bfloat16 l2 = __float2bfloat16_rn(x2 - __bfloat162float(h2));
                __nv_bfloat16 l3 = __float2bfloat16_rn(x3 - __bfloat162float(h3));
                *(__nv_bfloat162*)(Lw + o0) = __nv_bfloat162(l0, l1);
                *(__nv_bfloat162*)(Lw + o1) = __nv_bfloat162(l2, l3);
            }
    }
}

// ---------------------------------------------------------------------------
// fp32 -> bf16 hi/lo split (elementwise)
// ---------------------------------------------------------------------------
__global__ __launch_bounds__(256)
void split_plain(const float* __restrict__ in, __nv_bfloat16* __restrict__ hi,
                 __nv_bfloat16* __restrict__ lo, size_t n)
{
    size_t i = ((size_t)blockIdx.x * 256 + threadIdx.x) * 4;
    if (i >= n) return;
    float4 x = *(const float4*)(in + i);
    __nv_bfloat16 h0 = __float2bfloat16_rn(x.x), h1 = __float2bfloat16_rn(x.y);
    __nv_bfloat16 h2 = __float2bfloat16_rn(x.z), h3 = __float2bfloat16_rn(x.w);
    __nv_bfloat16 l0 = __float2bfloat16_rn(x.x - __bfloat162float(h0));
    __nv_bfloat16 l1 = __float2bfloat16_rn(x.y - __bfloat162float(h1));
    __nv_bfloat16 l2 = __float2bfloat16_rn(x.z - __bfloat162float(h2));
    __nv_bfloat16 l3 = __float2bfloat16_rn(x.w - __bfloat162float(h3));
    *(__nv_bfloat162*)(hi + i)     = __nv_bfloat162(h0, h1);
    *(__nv_bfloat162*)(hi + i + 2) = __nv_bfloat162(h2, h3);
    *(__nv_bfloat162*)(lo + i)     = __nv_bfloat162(l0, l1);
    *(__nv_bfloat162*)(lo + i + 2) = __nv_bfloat162(l2, l3);
}

// ---------------------------------------------------------------------------
// fp32 [R,C] -> transposed bf16 hi/lo [C,R] (batched via z)
// ---------------------------------------------------------------------------
__global__ __launch_bounds__(256)
void transpose_split(const float* __restrict__ in, __nv_bfloat16* __restrict__ hiT,
                     __nv_bfloat16* __restrict__ loT, int R, int C,
                     long long sIn, long long sOut)
{
    __shared__ float t[32][33];
    in  += (size_t)blockIdx.z * sIn;
    hiT += (size_t)blockIdx.z * sOut;
    loT += (size_t)blockIdx.z * sOut;
    const int r0 = blockIdx.y * 32, c0 = blockIdx.x * 32;
    const int tx = threadIdx.x & 31, ty = threadIdx.x >> 5;
#pragma unroll
    for (int i = ty; i < 32; i += 8)
        t[i][tx] = in[(size_t)(r0 + i) * C + c0 + tx];
    __syncthreads();
#pragma unroll
    for (int i = ty; i < 32; i += 8) {
        float x = t[tx][i];
        __nv_bfloat16 h = __float2bfloat16_rn(x);
        __nv_bfloat16 l = __float2bfloat16_rn(x - __bfloat162float(h));
        size_t o = (size_t)(c0 + i) * R + r0 + tx;
        hiT[o] = h; loT[o] = l;
    }
}

// ---------------------------------------------------------------------------
// Row softmax (4096 cols) fused with bf16 hi/lo split of the weights
// ---------------------------------------------------------------------------
__global__ __launch_bounds__(256)
void softmax_split(const float* __restrict__ S, __nv_bfloat16* __restrict__ Ph,
                   __nv_bfloat16* __restrict__ Pl)
{
    const size_t row = blockIdx.x;
    const float* p = S + row * (size_t)SS;
    const int tid = threadIdx.x;

    float4 v[4];
    float m = -INFINITY;
#pragma unroll
    for (int i = 0; i < 4; i++) {
        v[i] = ((const float4*)p)[tid + i * 256];
        m = fmaxf(m, fmaxf(fmaxf(v[i].x, v[i].y), fmaxf(v[i].z, v[i].w)));
    }
    __shared__ float red[256];
    red[tid] = m; __syncthreads();
#pragma unroll
    for (int s = 128; s > 0; s >>= 1) {
        if (tid < s) red[tid] = fmaxf(red[tid], red[tid + s]);
        __syncthreads();
    }
    const float rowmax = red[0];
    __syncthreads();

    float sum = 0.0f;
#pragma unroll
    for (int i = 0; i < 4; i++) {
        v[i].x = __expf(v[i].x - rowmax);
        v[i].y = __expf(v[i].y - rowmax);
        v[i].z = __expf(v[i].z - rowmax);
        v[i].w = __expf(v[i].w - rowmax);
        sum += v[i].x + v[i].y + v[i].z + v[i].w;
    }
    red[tid] = sum; __syncthreads();
#pragma unroll
    for (int s = 128; s > 0; s >>= 1) {
        if (tid < s) red[tid] += red[tid + s];
        __syncthreads();
    }
    const float inv = 1.0f / red[0];
    __syncthreads();

#pragma unroll
    for (int i = 0; i < 4; i++) {
        float f0 = v[i].x * inv, f1 = v[i].y * inv, f2 = v[i].z * inv, f3 = v[i].w * inv;
        __nv_bfloat16 h0 = __float2bfloat16_rn(f0), h1 = __float2bfloat16_rn(f1);
        __nv_bfloat16 h2 = __float2bfloat16_rn(f2), h3 = __float2bfloat16_rn(f3);
        __nv_bfloat16 l0 = __float2bfloat16_rn(f0 - __bfloat162float(h0));
        __nv_bfloat16 l1 = __float2bfloat16_rn(f1 - __bfloat162float(h1));
        __nv_bfloat16 l2 = __float2bfloat16_rn(f2 - __bfloat162float(h2));
        __nv_bfloat16 l3 = __float2bfloat16_rn(f3 - __bfloat162float(h3));
        size_t o = row * (size_t)SS + (size_t)(tid + i * 256) * 4;
        *(__nv_bfloat162*)(Ph + o)     = __nv_bfloat162(h0, h1);
        *(__nv_bfloat162*)(Ph + o + 2) = __nv_bfloat162(h2, h3);
        *(__nv_bfloat162*)(Pl + o)     = __nv_bfloat162(l0, l1);
        *(__nv_bfloat162*)(Pl + o + 2) = __nv_bfloat162(l2, l3);
    }
}

// ---------------------------------------------------------------------------
// kernel_launch — graph-capturable pipeline
// ---------------------------------------------------------------------------
extern "C" void kernel_launch(void* const* d_in, const int* in_sizes, int n_in,
                              void* d_out, int out_size)
{
    const float* X  = (const float*)d_in[0];
    const float* Wq = (const float*)d_in[1];
    const float* Wk = (const float*)d_in[2];
    const float* Wv = (const float*)d_in[3];
    float* out = (float*)d_out;

    float *Vf, *Sc;
    __nv_bfloat16 *Xhi, *Xlo, *Wh, *Wl, *Qhi, *Qlo, *Khi, *Klo, *Vthi, *Vtlo, *Phi, *Plo;
    cudaGetSymbolAddress((void**)&Vf, g_Vf);
    cudaGetSymbolAddress((void**)&Sc, g_S);
    cudaGetSymbolAddress((void**)&Xhi, g_Xhi);
    cudaGetSymbolAddress((void**)&Xlo, g_Xlo);
    cudaGetSymbolAddress((void**)&Wh, g_Wh);
    cudaGetSymbolAddress((void**)&Wl, g_Wl);
    cudaGetSymbolAddress((void**)&Qhi, g_Qhi);
    cudaGetSymbolAddress((void**)&Qlo, g_Qlo);
    cudaGetSymbolAddress((void**)&Khi, g_Khi);
    cudaGetSymbolAddress((void**)&Klo, g_Klo);
    cudaGetSymbolAddress((void**)&Vthi, g_Vthi);
    cudaGetSymbolAddress((void**)&Vtlo, g_Vtlo);
    cudaGetSymbolAddress((void**)&Phi, g_Phi);
    cudaGetSymbolAddress((void**)&Plo, g_Plo);

    cudaFuncSetAttribute(gemm_mma<false>, cudaFuncAttributeMaxDynamicSharedMemorySize, SMEM_DYN);
    cudaFuncSetAttribute(gemm_mma<true>,  cudaFuncAttributeMaxDynamicSharedMemorySize, SMEM_DYN);

    const size_t WSZ = (size_t)AA * DD;

    // 1) split X; transpose+split the three weight matrices to [A,D]
    split_plain<<<(MTOT * (size_t)DD) / 1024, 256>>>(X, Xhi, Xlo, (size_t)MTOT * DD);
    {
        dim3 g(AA / 32, DD / 32, 1);
        transpose_split<<<g, 256>>>(Wq, Wh + 0 * WSZ, Wl + 0 * WSZ, DD, AA, 0, 0);
        transpose_split<<<g, 256>>>(Wk, Wh + 1 * WSZ, Wl + 1 * WSZ, DD, AA, 0, 0);
        transpose_split<<<g, 256>>>(Wv, Wh + 2 * WSZ, Wl + 2 * WSZ, DD, AA, 0, 0);
    }

    // 2) projections: Q,K write bf16 hi/lo directly; V stays fp32 for transpose
    {
        dim3 g(AA / 128, MTOT / 128, 1);
        gemm_mma<true><<<g, 256, SMEM_DYN>>>(Xhi, Xlo, Wh + 0*WSZ, Wl + 0*WSZ,
                                             nullptr, Qhi, Qlo, DD, AA, 0, 0, 0);
        gemm_mma<true><<<g, 256, SMEM_DYN>>>(Xhi, Xlo, Wh + 1*WSZ, Wl + 1*WSZ,
                                             nullptr, Khi, Klo, DD, AA, 0, 0, 0);
        gemm_mma<false><<<g, 256, SMEM_DYN>>>(Xhi, Xlo, Wh + 2*WSZ, Wl + 2*WSZ,
                                              Vf, nullptr, nullptr, DD, AA, 0, 0, 0);
    }

    // 3) transpose+split V per batch to [A,S]
    {
        dim3 g(AA / 32, SS / 32, BB);
        transpose_split<<<g, 256>>>(Vf, Vthi, Vtlo, SS, AA,
                                    (long long)SS * AA, (long long)SS * AA);
    }

    // 4) scores: S = Q @ K^T per batch
    {
        dim3 g(SS / 128, SS / 128, BB);
        gemm_mma<false><<<g, 256, SMEM_DYN>>>(Qhi, Qlo, Khi, Klo, Sc, nullptr, nullptr,
                                              AA, SS,
                                              (long long)SS * AA, (long long)SS * AA,
                                              (long long)SS * SS);
    }

    // 5) softmax + split to bf16 hi/lo
    softmax_split<<<BB * SS, 256>>>(Sc, Phi, Plo);

    // 6) output: O = P @ V per batch (V^T is K-major)
    {
        dim3 g(AA / 128, SS / 128, BB);
        gemm_mma<false><<<g, 256, SMEM_DYN>>>(Phi, Plo, Vthi, Vtlo, out, nullptr, nullptr,
                                              SS, AA,
                                              (long long)SS * SS, (long long)AA * SS,
                                              (long long)SS * AA);
    }
}

// round 5
// speedup vs baseline: 2.5990x; 1.0033x over previous
#include <cuda_runtime.h>
#include <cuda_bf16.h>
#include <cstdint>
#include <math.h>

// Problem dims (fixed)
#define BB 4
#define SS 4096
#define DD 1024
#define AA 1024
#define MTOT (BB*SS)   // 16384

// ---------------------------------------------------------------------------
// Device scratch
// ---------------------------------------------------------------------------
__device__ float g_Vf[(size_t)MTOT * AA];                 // 64 MB
__device__ float g_S [(size_t)BB * SS * SS];              // 256 MB scores
__device__ __nv_bfloat16 g_Xhi[(size_t)MTOT * DD];
__device__ __nv_bfloat16 g_Xlo[(size_t)MTOT * DD];
__device__ __nv_bfloat16 g_Wh[3][(size_t)AA * DD];        // W^T splits [A,D]
__device__ __nv_bfloat16 g_Wl[3][(size_t)AA * DD];
__device__ __nv_bfloat16 g_Qhi[(size_t)MTOT * AA];
__device__ __nv_bfloat16 g_Qlo[(size_t)MTOT * AA];
__device__ __nv_bfloat16 g_Khi[(size_t)MTOT * AA];
__device__ __nv_bfloat16 g_Klo[(size_t)MTOT * AA];
__device__ __nv_bfloat16 g_Vthi[(size_t)BB * AA * SS];    // V^T per batch [A,S]
__device__ __nv_bfloat16 g_Vtlo[(size_t)BB * AA * SS];
__device__ __nv_bfloat16 g_Phi[(size_t)BB * SS * SS];     // 128 MB
__device__ __nv_bfloat16 g_Plo[(size_t)BB * SS * SS];     // 128 MB

// ---------------------------------------------------------------------------
// Helpers
// ---------------------------------------------------------------------------
__device__ __forceinline__ uint32_t smem_u32(const void* p) {
    uint32_t a;
    asm("{ .reg .u64 t; cvta.to.shared.u64 t, %1; cvt.u32.u64 %0, t; }" : "=r"(a) : "l"(p));
    return a;
}

#define CP_ASYNC16(saddr, gaddr) \
    asm volatile("cp.async.cg.shared.global [%0], [%1], 16;" :: "r"(saddr), "l"(gaddr))
#define CP_COMMIT()  asm volatile("cp.async.commit_group;" ::: "memory")
#define CP_WAIT1()   asm volatile("cp.async.wait_group 1;" ::: "memory")
#define CP_WAIT0()   asm volatile("cp.async.wait_group 0;" ::: "memory")

#define MMA_BF16(c, a, b) \
    asm volatile("mma.sync.aligned.m16n8k16.row.col.f32.bf16.bf16.f32 " \
        "{%0,%1,%2,%3}, {%4,%5,%6,%7}, {%8,%9}, {%0,%1,%2,%3};" \
        : "+f"((c)[0]), "+f"((c)[1]), "+f"((c)[2]), "+f"((c)[3]) \
        : "r"((a)[0]), "r"((a)[1]), "r"((a)[2]), "r"((a)[3]), \
          "r"((b)[0]), "r"((b)[1]))

// ---------------------------------------------------------------------------
// HMMA GEMM, bf16 hi/lo 3-term split (hh + hl + lh).
// C[M,N] = (Ahi+Alo)[M,K] * (Bhi+Blo)[N,K]^T, K-major.
// CTA tile 128x256, K chunk 64, 2-stage double buffer.
// 8 warps in 2(m) x 4(n) grid; warp tile 64x64 = 4 m16 x 8 n8 mma tiles.
// LDS/MMA = 0.667 (vs 1.0 before) -> tensor-pipe-bound.
// ---------------------------------------------------------------------------
#define KC       64
#define ROWB     144                         // 64 bf16 + pad = 144 B
#define A_TILE   (128 * ROWB)                // 18432 B
#define B_TILE   (256 * ROWB)                // 36864 B
#define STAGE_B  (2 * A_TILE + 2 * B_TILE)   // 110592 B
#define SMEM_DYN (2 * STAGE_B)               // 221184 B

__device__ __forceinline__ void load_tile_async(const __nv_bfloat16* __restrict__ g,
                                                int ldK, char* sb, int tid, int rows)
{
    const int nch = rows * 8;                // 16B chunks
#pragma unroll
    for (int ch = tid; ch < nch; ch += 256) {
        int row = ch >> 3, c = ch & 7;
        uint32_t sa = smem_u32(sb + row * ROWB + c * 16);
        CP_ASYNC16(sa, g + (size_t)row * ldK + c * 8);
    }
}

__device__ __forceinline__ void load_stage(const __nv_bfloat16* pAh, const __nv_bfloat16* pAl,
                                           const __nv_bfloat16* pBh, const __nv_bfloat16* pBl,
                                           int k0, int K, char* sp, int tid)
{
    load_tile_async(pAh + k0, K, sp,                       tid, 128);
    load_tile_async(pAl + k0, K, sp + A_TILE,              tid, 128);
    load_tile_async(pBh + k0, K, sp + 2*A_TILE,            tid, 256);
    load_tile_async(pBl + k0, K, sp + 2*A_TILE + B_TILE,   tid, 256);
    CP_COMMIT();
}

template <bool SPLIT_OUT>
__global__ __launch_bounds__(256, 1)
void gemm_mma(const __nv_bfloat16* __restrict__ Ahi, const __nv_bfloat16* __restrict__ Alo,
              const __nv_bfloat16* __restrict__ Bhi, const __nv_bfloat16* __restrict__ Blo,
              float* __restrict__ C,
              __nv_bfloat16* __restrict__ Chi, __nv_bfloat16* __restrict__ Clo,
              int K, int ldC,
              long long sA, long long sB, long long sC)
{
    extern __shared__ __align__(128) char smem[];
    const int tid = threadIdx.x;
    const int wid = tid >> 5, lane = tid & 31;
    const int wm = wid & 1, wn = wid >> 1;     // 2 x 4 warp grid
    const int m0 = blockIdx.y * 128;
    const int n0 = blockIdx.x * 256;

    const __nv_bfloat16* pAh = Ahi + (size_t)blockIdx.z * sA + (size_t)m0 * K;
    const __nv_bfloat16* pAl = Alo + (size_t)blockIdx.z * sA + (size_t)m0 * K;
    const __nv_bfloat16* pBh = Bhi + (size_t)blockIdx.z * sB + (size_t)n0 * K;
    const __nv_bfloat16* pBl = Blo + (size_t)blockIdx.z * sB + (size_t)n0 * K;

    float acc[4][8][4];
#pragma unroll
    for (int mt = 0; mt < 4; mt++)
#pragma unroll
        for (int nt = 0; nt < 8; nt++)
#pragma unroll
            for (int j = 0; j < 4; j++) acc[mt][nt][j] = 0.0f;

    const int nch = K >> 6;

    // prologue: chunks 0,1 into stages 0,1
    load_stage(pAh, pAl, pBh, pBl, 0,  K, smem,           tid);
    load_stage(pAh, pAl, pBh, pBl, KC, K, smem + STAGE_B, tid);

    const int r  = lane >> 2;        // 0..7
    const int kq = lane & 3;         // 0..3

    for (int c = 0; c < nch; ++c) {
        if (c + 1 < nch) CP_WAIT1(); else CP_WAIT0();
        __syncthreads();

        const char* sp  = smem + (c & 1) * STAGE_B;
        const char* sAh = sp;
        const char* sAl = sp +     A_TILE;
        const char* sBh = sp + 2 * A_TILE;
        const char* sBl = sp + 2 * A_TILE + B_TILE;

#pragma unroll
        for (int ks = 0; ks < 4; ++ks) {
            const int kb = (ks * 8 + kq) * 4;

            uint32_t ah[4][4], al[4][4];
#pragma unroll
            for (int mt = 0; mt < 4; mt++) {
                const int row = wm * 64 + mt * 16 + r;
                const char* a0 = sAh + row * ROWB + kb;
                const char* a1 = sAh + (row + 8) * ROWB + kb;
                ah[mt][0] = *(const uint32_t*)(a0);
                ah[mt][1] = *(const uint32_t*)(a1);
                ah[mt][2] = *(const uint32_t*)(a0 + 16);
                ah[mt][3] = *(const uint32_t*)(a1 + 16);
                const char* b0 = sAl + row * ROWB + kb;
                const char* b1 = sAl + (row + 8) * ROWB + kb;
                al[mt][0] = *(const uint32_t*)(b0);
                al[mt][1] = *(const uint32_t*)(b1);
                al[mt][2] = *(const uint32_t*)(b0 + 16);
                al[mt][3] = *(const uint32_t*)(b1 + 16);
            }
#pragma unroll
            for (int nt = 0; nt < 8; nt++) {
                const int n = wn * 64 + nt * 8 + r;
                uint32_t bh[2], bl[2];
                const char* p = sBh + n * ROWB + kb;
                bh[0] = *(const uint32_t*)(p);
                bh[1] = *(const uint32_t*)(p + 16);
                const char* q = sBl + n * ROWB + kb;
                bl[0] = *(const uint32_t*)(q);
                bl[1] = *(const uint32_t*)(q + 16);
#pragma unroll
                for (int mt = 0; mt < 4; mt++) {
                    MMA_BF16(acc[mt][nt], ah[mt], bh);
                    MMA_BF16(acc[mt][nt], ah[mt], bl);
                    MMA_BF16(acc[mt][nt], al[mt], bh);
                }
            }
        }

        if (c + 2 < nch) {
            __syncthreads();   // all warps done reading stage (c&1)
            load_stage(pAh, pAl, pBh, pBl, (c + 2) * KC, K,
                       smem + (c & 1) * STAGE_B, tid);
        }
    }

    // epilogue
    const int cq = (lane & 3) * 2;
    if (!SPLIT_OUT) {
        float* Cw = C + (size_t)blockIdx.z * sC
                      + (size_t)(m0 + wm * 64) * ldC + n0 + wn * 64;
#pragma unroll
        for (int mt = 0; mt < 4; mt++)
#pragma unroll
            for (int nt = 0; nt < 8; nt++) {
                float* p0 = Cw + (size_t)(mt * 16 + r) * ldC + nt * 8 + cq;
                float* p1 = p0 + 8 * (size_t)ldC;
                *(float2*)p0 = make_float2(acc[mt][nt][0], acc[mt][nt][1]);
                *(float2*)p1 = make_float2(acc[mt][nt][2], acc[mt][nt][3]);
            }
    } else {
        const size_t off = (size_t)blockIdx.z * sC
                         + (size_t)(m0 + wm * 64) * ldC + n0 + wn * 64;
        __nv_bfloat16* Hw = Chi + off;
        __nv_bfloat16* Lw = Clo + off;
#pragma unroll
        for (int mt = 0; mt < 4; mt++)
#pragma unroll
            for (int nt = 0; nt < 8; nt++) {
                const size_t o0 = (size_t)(mt * 16 + r) * ldC + nt * 8 + cq;
                const size_t o1 = o0 + 8 * (size_t)ldC;
                float x0 = acc[mt][nt][0], x1 = acc[mt][nt][1];
                float x2 = acc[mt][nt][2], x3 = acc[mt][nt][3];
                __nv_bfloat16 h0 = __float2bfloat16_rn(x0), h1 = __float2bfloat16_rn(x1);
                __nv_bfloat16 h2 = __float2bfloat16_rn(x2), h3 = __float2bfloat16_rn(x3);
                *(__nv_bfloat162*)(Hw + o0) = __nv_bfloat162(h0, h1);
                *(__nv_bfloat162*)(Hw + o1) = __nv_bfloat162(h2, h3);
                __nv_bfloat16 l0 = __float2bfloat16_rn(x0 - __bfloat162float(h0));
                __nv_bfloat16 l1 = __float2bfloat16_rn(x1 - __bfloat162float(h1));
                __nv_bfloat16 l2 = __float2bfloat16_rn(x2 - __bfloat162float(h2));
                __nv_bfloat16 l3 = __float2bfloat16_rn(x3 - __bfloat162float(h3));
                *(__nv_bfloat162*)(Lw + o0) = __nv_bfloat162(l0, l1);
                *(__nv_bfloat162*)(Lw + o1) = __nv_bfloat162(l2, l3);
            }
    }
}

// ---------------------------------------------------------------------------
// fp32 -> bf16 hi/lo split (elementwise)
// ---------------------------------------------------------------------------
__global__ __launch_bounds__(256)
void split_plain(const float* __restrict__ in, __nv_bfloat16* __restrict__ hi,
                 __nv_bfloat16* __restrict__ lo, size_t n)
{
    size_t i = ((size_t)blockIdx.x * 256 + threadIdx.x) * 4;
    if (i >= n) return;
    float4 x = *(const float4*)(in + i);
    __nv_bfloat16 h0 = __float2bfloat16_rn(x.x), h1 = __float2bfloat16_rn(x.y);
    __nv_bfloat16 h2 = __float2bfloat16_rn(x.z), h3 = __float2bfloat16_rn(x.w);
    __nv_bfloat16 l0 = __float2bfloat16_rn(x.x - __bfloat162float(h0));
    __nv_bfloat16 l1 = __float2bfloat16_rn(x.y - __bfloat162float(h1));
    __nv_bfloat16 l2 = __float2bfloat16_rn(x.z - __bfloat162float(h2));
    __nv_bfloat16 l3 = __float2bfloat16_rn(x.w - __bfloat162float(h3));
    *(__nv_bfloat162*)(hi + i)     = __nv_bfloat162(h0, h1);
    *(__nv_bfloat162*)(hi + i + 2) = __nv_bfloat162(h2, h3);
    *(__nv_bfloat162*)(lo + i)     = __nv_bfloat162(l0, l1);
    *(__nv_bfloat162*)(lo + i + 2) = __nv_bfloat162(l2, l3);
}

// ---------------------------------------------------------------------------
// fp32 [R,C] -> transposed bf16 hi/lo [C,R] (batched via z)
// ---------------------------------------------------------------------------
__global__ __launch_bounds__(256)
void transpose_split(const float* __restrict__ in, __nv_bfloat16* __restrict__ hiT,
                     __nv_bfloat16* __restrict__ loT, int R, int C,
                     long long sIn, long long sOut)
{
    __shared__ float t[32][33];
    in  += (size_t)blockIdx.z * sIn;
    hiT += (size_t)blockIdx.z * sOut;
    loT += (size_t)blockIdx.z * sOut;
    const int r0 = blockIdx.y * 32, c0 = blockIdx.x * 32;
    const int tx = threadIdx.x & 31, ty = threadIdx.x >> 5;
#pragma unroll
    for (int i = ty; i < 32; i += 8)
        t[i][tx] = in[(size_t)(r0 + i) * C + c0 + tx];
    __syncthreads();
#pragma unroll
    for (int i = ty; i < 32; i += 8) {
        float x = t[tx][i];
        __nv_bfloat16 h = __float2bfloat16_rn(x);
        __nv_bfloat16 l = __float2bfloat16_rn(x - __bfloat162float(h));
        size_t o = (size_t)(c0 + i) * R + r0 + tx;
        hiT[o] = h; loT[o] = l;
    }
}

// ---------------------------------------------------------------------------
// Row softmax (4096 cols) fused with bf16 hi/lo split of the weights
// ---------------------------------------------------------------------------
__global__ __launch_bounds__(256)
void softmax_split(const float* __restrict__ S, __nv_bfloat16* __restrict__ Ph,
                   __nv_bfloat16* __restrict__ Pl)
{
    const size_t row = blockIdx.x;
    const float* p = S + row * (size_t)SS;
    const int tid = threadIdx.x;

    float4 v[4];
    float m = -INFINITY;
#pragma unroll
    for (int i = 0; i < 4; i++) {
        v[i] = ((const float4*)p)[tid + i * 256];
        m = fmaxf(m, fmaxf(fmaxf(v[i].x, v[i].y), fmaxf(v[i].z, v[i].w)));
    }
    __shared__ float red[256];
    red[tid] = m; __syncthreads();
#pragma unroll
    for (int s = 128; s > 0; s >>= 1) {
        if (tid < s) red[tid] = fmaxf(red[tid], red[tid + s]);
        __syncthreads();
    }
    const float rowmax = red[0];
    __syncthreads();

    float sum = 0.0f;
#pragma unroll
    for (int i = 0; i < 4; i++) {
        v[i].x = __expf(v[i].x - rowmax);
        v[i].y = __expf(v[i].y - rowmax);
        v[i].z = __expf(v[i].z - rowmax);
        v[i].w = __expf(v[i].w - rowmax);
        sum += v[i].x + v[i].y + v[i].z + v[i].w;
    }
    red[tid] = sum; __syncthreads();
#pragma unroll
    for (int s = 128; s > 0; s >>= 1) {
        if (tid < s) red[tid] += red[tid + s];
        __syncthreads();
    }
    const float inv = 1.0f / red[0];
    __syncthreads();

#pragma unroll
    for (int i = 0; i < 4; i++) {
        float f0 = v[i].x * inv, f1 = v[i].y * inv, f2 = v[i].z * inv, f3 = v[i].w * inv;
        __nv_bfloat16 h0 = __float2bfloat16_rn(f0), h1 = __float2bfloat16_rn(f1);
        __nv_bfloat16 h2 = __float2bfloat16_rn(f2), h3 = __float2bfloat16_rn(f3);
        __nv_bfloat16 l0 = __float2bfloat16_rn(f0 - __bfloat162float(h0));
        __nv_bfloat16 l1 = __float2bfloat16_rn(f1 - __bfloat162float(h1));
        __nv_bfloat16 l2 = __float2bfloat16_rn(f2 - __bfloat162float(h2));
        __nv_bfloat16 l3 = __float2bfloat16_rn(f3 - __bfloat162float(h3));
        size_t o = row * (size_t)SS + (size_t)(tid + i * 256) * 4;
        *(__nv_bfloat162*)(Ph + o)     = __nv_bfloat162(h0, h1);
        *(__nv_bfloat162*)(Ph + o + 2) = __nv_bfloat162(h2, h3);
        *(__nv_bfloat162*)(Pl + o)     = __nv_bfloat162(l0, l1);
        *(__nv_bfloat162*)(Pl + o + 2) = __nv_bfloat162(l2, l3);
    }
}

// ---------------------------------------------------------------------------
// kernel_launch — graph-capturable pipeline
// ---------------------------------------------------------------------------
extern "C" void kernel_launch(void* const* d_in, const int* in_sizes, int n_in,
                              void* d_out, int out_size)
{
    const float* X  = (const float*)d_in[0];
    const float* Wq = (const float*)d_in[1];
    const float* Wk = (const float*)d_in[2];
    const float* Wv = (const float*)d_in[3];
    float* out = (float*)d_out;

    float *Vf, *Sc;
    __nv_bfloat16 *Xhi, *Xlo, *Wh, *Wl, *Qhi, *Qlo, *Khi, *Klo, *Vthi, *Vtlo, *Phi, *Plo;
    cudaGetSymbolAddress((void**)&Vf, g_Vf);
    cudaGetSymbolAddress((void**)&Sc, g_S);
    cudaGetSymbolAddress((void**)&Xhi, g_Xhi);
    cudaGetSymbolAddress((void**)&Xlo, g_Xlo);
    cudaGetSymbolAddress((void**)&Wh, g_Wh);
    cudaGetSymbolAddress((void**)&Wl, g_Wl);
    cudaGetSymbolAddress((void**)&Qhi, g_Qhi);
    cudaGetSymbolAddress((void**)&Qlo, g_Qlo);
    cudaGetSymbolAddress((void**)&Khi, g_Khi);
    cudaGetSymbolAddress((void**)&Klo, g_Klo);
    cudaGetSymbolAddress((void**)&Vthi, g_Vthi);
    cudaGetSymbolAddress((void**)&Vtlo, g_Vtlo);
    cudaGetSymbolAddress((void**)&Phi, g_Phi);
    cudaGetSymbolAddress((void**)&Plo, g_Plo);

    cudaFuncSetAttribute(gemm_mma<false>, cudaFuncAttributeMaxDynamicSharedMemorySize, SMEM_DYN);
    cudaFuncSetAttribute(gemm_mma<true>,  cudaFuncAttributeMaxDynamicSharedMemorySize, SMEM_DYN);

    const size_t WSZ = (size_t)AA * DD;

    // 1) split X; transpose+split the three weight matrices to [A,D]
    split_plain<<<(MTOT * (size_t)DD) / 1024, 256>>>(X, Xhi, Xlo, (size_t)MTOT * DD);
    {
        dim3 g(AA / 32, DD / 32, 1);
        transpose_split<<<g, 256>>>(Wq, Wh + 0 * WSZ, Wl + 0 * WSZ, DD, AA, 0, 0);
        transpose_split<<<g, 256>>>(Wk, Wh + 1 * WSZ, Wl + 1 * WSZ, DD, AA, 0, 0);
        transpose_split<<<g, 256>>>(Wv, Wh + 2 * WSZ, Wl + 2 * WSZ, DD, AA, 0, 0);
    }

    // 2) projections: Q,K write bf16 hi/lo directly; V stays fp32 for transpose
    {
        dim3 g(AA / 256, MTOT / 128, 1);
        gemm_mma<true><<<g, 256, SMEM_DYN>>>(Xhi, Xlo, Wh + 0*WSZ, Wl + 0*WSZ,
                                             nullptr, Qhi, Qlo, DD, AA, 0, 0, 0);
        gemm_mma<true><<<g, 256, SMEM_DYN>>>(Xhi, Xlo, Wh + 1*WSZ, Wl + 1*WSZ,
                                             nullptr, Khi, Klo, DD, AA, 0, 0, 0);
        gemm_mma<false><<<g, 256, SMEM_DYN>>>(Xhi, Xlo, Wh + 2*WSZ, Wl + 2*WSZ,
                                              Vf, nullptr, nullptr, DD, AA, 0, 0, 0);
    }

    // 3) transpose+split V per batch to [A,S]
    {
        dim3 g(AA / 32, SS / 32, BB);
        transpose_split<<<g, 256>>>(Vf, Vthi, Vtlo, SS, AA,
                                    (long long)SS * AA, (long long)SS * AA);
    }

    // 4) scores: S = Q @ K^T per batch
    {
        dim3 g(SS / 256, SS / 128, BB);
        gemm_mma<false><<<g, 256, SMEM_DYN>>>(Qhi, Qlo, Khi, Klo, Sc, nullptr, nullptr,
                                              AA, SS,
                                              (long long)SS * AA, (long long)SS * AA,
                                              (long long)SS * SS);
    }

    // 5) softmax + split to bf16 hi/lo
    softmax_split<<<BB * SS, 256>>>(Sc, Phi, Plo);

    // 6) output: O = P @ V per batch (V^T is K-major)
    {
        dim3 g(AA / 256, SS / 128, BB);
        gemm_mma<false><<<g, 256, SMEM_DYN>>>(Phi, Plo, Vthi, Vtlo, out, nullptr, nullptr,
                                              SS, AA,
                                              (long long)SS * SS, (long long)AA * SS,
                                              (long long)SS * AA);
    }
}

// round 6
// speedup vs baseline: 2.9613x; 1.1394x over previous
#include <cuda_runtime.h>
#include <cuda_fp16.h>
#include <cstdint>
#include <math.h>

// Problem dims (fixed)
#define BB 4
#define SS 4096
#define DD 1024
#define AA 1024
#define MTOT (BB*SS)   // 16384

// ---------------------------------------------------------------------------
// Device scratch
// ---------------------------------------------------------------------------
__device__ float g_Vf[(size_t)MTOT * AA];                 // 64 MB
__device__ float g_S [(size_t)BB * SS * SS];              // 256 MB scores
__device__ __half g_Xhi[(size_t)MTOT * DD];
__device__ __half g_Xlo[(size_t)MTOT * DD];
__device__ __half g_Wh[3][(size_t)AA * DD];               // (16*W)^T splits [A,D]
__device__ __half g_Wl[3][(size_t)AA * DD];
__device__ __half g_Qhi[(size_t)MTOT * AA];
__device__ __half g_Qlo[(size_t)MTOT * AA];
__device__ __half g_Khi[(size_t)MTOT * AA];
__device__ __half g_Klo[(size_t)MTOT * AA];
__device__ __half g_Vthi[(size_t)BB * AA * SS];           // V^T per batch [A,S], hi only
__device__ __half g_Phi[(size_t)BB * SS * SS];            // 128 MB
__device__ __half g_Plo[(size_t)BB * SS * SS];            // 128 MB

// ---------------------------------------------------------------------------
// Helpers
// ---------------------------------------------------------------------------
__device__ __forceinline__ uint32_t smem_u32(const void* p) {
    uint32_t a;
    asm("{ .reg .u64 t; cvta.to.shared.u64 t, %1; cvt.u32.u64 %0, t; }" : "=r"(a) : "l"(p));
    return a;
}

#define CP_ASYNC16(saddr, gaddr) \
    asm volatile("cp.async.cg.shared.global [%0], [%1], 16;" :: "r"(saddr), "l"(gaddr))
#define CP_COMMIT()  asm volatile("cp.async.commit_group;" ::: "memory")
#define CP_WAIT1()   asm volatile("cp.async.wait_group 1;" ::: "memory")
#define CP_WAIT0()   asm volatile("cp.async.wait_group 0;" ::: "memory")

#define MMA_F16(c, a, b) \
    asm volatile("mma.sync.aligned.m16n8k16.row.col.f32.f16.f16.f32 " \
        "{%0,%1,%2,%3}, {%4,%5,%6,%7}, {%8,%9}, {%0,%1,%2,%3};" \
        : "+f"((c)[0]), "+f"((c)[1]), "+f"((c)[2]), "+f"((c)[3]) \
        : "r"((a)[0]), "r"((a)[1]), "r"((a)[2]), "r"((a)[3]), \
          "r"((b)[0]), "r"((b)[1]))

// ---------------------------------------------------------------------------
// HMMA GEMM, fp16 hi/lo split.
// BT=2: 3 terms (AhBh + AhBl + AlBh), B has hi+lo.
// BT=1: 2 terms (AhBh + AlBh), B hi only (used for P@V).
// CTA tile 128x128, K chunk 32, 2-stage double buffer, 2 CTAs/SM.
// 8 warps as 4(m) x 2(n); warp tile 32x64 = 2 m16 x 8 n8 mma tiles.
// ---------------------------------------------------------------------------
#define KC    32
#define ROWB  80                              // 32 fp16 (64B) + 16B pad
#define TILE_T (128 * ROWB)                   // 10240 B

__device__ __forceinline__ void load_tile32(const __half* __restrict__ g,
                                            int ldK, char* sb, int tid)
{
#pragma unroll
    for (int i = 0; i < 2; i++) {
        int ch = tid + i * 256;               // 0..511
        int row = ch >> 2, c = ch & 3;
        CP_ASYNC16(smem_u32(sb + row * ROWB + c * 16),
                   g + (size_t)row * ldK + c * 8);
    }
}

template <int BT>
__device__ __forceinline__ void load_stage(const __half* pAh, const __half* pAl,
                                           const __half* pBh, const __half* pBl,
                                           int k0, int K, char* sp, int tid)
{
    load_tile32(pAh + k0, K, sp,              tid);
    load_tile32(pAl + k0, K, sp +   TILE_T,   tid);
    load_tile32(pBh + k0, K, sp + 2*TILE_T,   tid);
    if (BT == 2)
        load_tile32(pBl + k0, K, sp + 3*TILE_T, tid);
    CP_COMMIT();
}

template <int BT, bool SPLIT_OUT>
__global__ __launch_bounds__(256, 2)
void gemm_mma(const __half* __restrict__ Ahi, const __half* __restrict__ Alo,
              const __half* __restrict__ Bhi, const __half* __restrict__ Blo,
              float* __restrict__ C,
              __half* __restrict__ Chi, __half* __restrict__ Clo,
              int K, int ldC,
              long long sA, long long sB, long long sC, float oscale)
{
    constexpr int STG = (2 + BT) * TILE_T;
    extern __shared__ __align__(128) char smem[];
    const int tid = threadIdx.x;
    const int wid = tid >> 5, lane = tid & 31;
    const int wm = wid & 3, wn = wid >> 2;    // 4(m) x 2(n)
    const int m0 = blockIdx.y * 128;
    const int n0 = blockIdx.x * 128;

    const __half* pAh = Ahi + (size_t)blockIdx.z * sA + (size_t)m0 * K;
    const __half* pAl = Alo + (size_t)blockIdx.z * sA + (size_t)m0 * K;
    const __half* pBh = Bhi + (size_t)blockIdx.z * sB + (size_t)n0 * K;
    const __half* pBl = (BT == 2) ? Blo + (size_t)blockIdx.z * sB + (size_t)n0 * K : nullptr;

    float acc[2][8][4];
#pragma unroll
    for (int mt = 0; mt < 2; mt++)
#pragma unroll
        for (int nt = 0; nt < 8; nt++)
#pragma unroll
            for (int j = 0; j < 4; j++) acc[mt][nt][j] = 0.0f;

    const int nch = K >> 5;

    load_stage<BT>(pAh, pAl, pBh, pBl, 0,  K, smem,       tid);
    load_stage<BT>(pAh, pAl, pBh, pBl, KC, K, smem + STG, tid);

    const int r  = lane >> 2;        // 0..7
    const int kq = lane & 3;         // 0..3

    for (int c = 0; c < nch; ++c) {
        if (c + 1 < nch) CP_WAIT1(); else CP_WAIT0();
        __syncthreads();

        const char* sp  = smem + (c & 1) * STG;
        const char* sAh = sp;
        const char* sAl = sp +     TILE_T;
        const char* sBh = sp + 2 * TILE_T;
        const char* sBl = sp + 3 * TILE_T;

#pragma unroll
        for (int ks = 0; ks < 2; ++ks) {
            const int kb = ks * 32 + kq * 4;

            uint32_t ah[2][4], al[2][4];
#pragma unroll
            for (int mt = 0; mt < 2; mt++) {
                const int row = wm * 32 + mt * 16 + r;
                const char* a0 = sAh + row * ROWB + kb;
                const char* a1 = sAh + (row + 8) * ROWB + kb;
                ah[mt][0] = *(const uint32_t*)(a0);
                ah[mt][1] = *(const uint32_t*)(a1);
                ah[mt][2] = *(const uint32_t*)(a0 + 16);
                ah[mt][3] = *(const uint32_t*)(a1 + 16);
                const char* b0 = sAl + row * ROWB + kb;
                const char* b1 = sAl + (row + 8) * ROWB + kb;
                al[mt][0] = *(const uint32_t*)(b0);
                al[mt][1] = *(const uint32_t*)(b1);
                al[mt][2] = *(const uint32_t*)(b0 + 16);
                al[mt][3] = *(const uint32_t*)(b1 + 16);
            }
#pragma unroll
            for (int nt = 0; nt < 8; nt++) {
                const int n = wn * 64 + nt * 8 + r;
                uint32_t bh[2];
                const char* p = sBh + n * ROWB + kb;
                bh[0] = *(const uint32_t*)(p);
                bh[1] = *(const uint32_t*)(p + 16);
#pragma unroll
                for (int mt = 0; mt < 2; mt++) {
                    MMA_F16(acc[mt][nt], ah[mt], bh);
                    MMA_F16(acc[mt][nt], al[mt], bh);
                }
                if (BT == 2) {
                    uint32_t bl[2];
                    const char* q = sBl + n * ROWB + kb;
                    bl[0] = *(const uint32_t*)(q);
                    bl[1] = *(const uint32_t*)(q + 16);
#pragma unroll
                    for (int mt = 0; mt < 2; mt++)
                        MMA_F16(acc[mt][nt], ah[mt], bl);
                }
            }
        }

        if (c + 2 < nch) {
            __syncthreads();
            load_stage<BT>(pAh, pAl, pBh, pBl, (c + 2) * KC, K,
                           smem + (c & 1) * STG, tid);
        }
    }

    // epilogue
    const int cq = (lane & 3) * 2;
    if (!SPLIT_OUT) {
        float* Cw = C + (size_t)blockIdx.z * sC
                      + (size_t)(m0 + wm * 32) * ldC + n0 + wn * 64;
#pragma unroll
        for (int mt = 0; mt < 2; mt++)
#pragma unroll
            for (int nt = 0; nt < 8; nt++) {
                float* p0 = Cw + (size_t)(mt * 16 + r) * ldC + nt * 8 + cq;
                float* p1 = p0 + 8 * (size_t)ldC;
                *(float2*)p0 = make_float2(acc[mt][nt][0] * oscale, acc[mt][nt][1] * oscale);
                *(float2*)p1 = make_float2(acc[mt][nt][2] * oscale, acc[mt][nt][3] * oscale);
            }
    } else {
        const size_t off = (size_t)blockIdx.z * sC
                         + (size_t)(m0 + wm * 32) * ldC + n0 + wn * 64;
        __half* Hw = Chi + off;
        __half* Lw = Clo + off;
#pragma unroll
        for (int mt = 0; mt < 2; mt++)
#pragma unroll
            for (int nt = 0; nt < 8; nt++) {
                const size_t o0 = (size_t)(mt * 16 + r) * ldC + nt * 8 + cq;
                const size_t o1 = o0 + 8 * (size_t)ldC;
                float x0 = acc[mt][nt][0] * oscale, x1 = acc[mt][nt][1] * oscale;
                float x2 = acc[mt][nt][2] * oscale, x3 = acc[mt][nt][3] * oscale;
                __half h0 = __float2half_rn(x0), h1 = __float2half_rn(x1);
                __half h2 = __float2half_rn(x2), h3 = __float2half_rn(x3);
                *(__half2*)(Hw + o0) = __halves2half2(h0, h1);
                *(__half2*)(Hw + o1) = __halves2half2(h2, h3);
                __half l0 = __float2half_rn(x0 - __half2float(h0));
                __half l1 = __float2half_rn(x1 - __half2float(h1));
                __half l2 = __float2half_rn(x2 - __half2float(h2));
                __half l3 = __float2half_rn(x3 - __half2float(h3));
                *(__half2*)(Lw + o0) = __halves2half2(l0, l1);
                *(__half2*)(Lw + o1) = __halves2half2(l2, l3);
            }
    }
}

// ---------------------------------------------------------------------------
// fp32 -> fp16 hi/lo split (elementwise)
// ---------------------------------------------------------------------------
__global__ __launch_bounds__(256)
void split_plain(const float* __restrict__ in, __half* __restrict__ hi,
                 __half* __restrict__ lo, size_t n)
{
    size_t i = ((size_t)blockIdx.x * 256 + threadIdx.x) * 4;
    if (i >= n) return;
    float4 x = *(const float4*)(in + i);
    __half h0 = __float2half_rn(x.x), h1 = __float2half_rn(x.y);
    __half h2 = __float2half_rn(x.z), h3 = __float2half_rn(x.w);
    __half l0 = __float2half_rn(x.x - __half2float(h0));
    __half l1 = __float2half_rn(x.y - __half2float(h1));
    __half l2 = __float2half_rn(x.z - __half2float(h2));
    __half l3 = __float2half_rn(x.w - __half2float(h3));
    *(__half2*)(hi + i)     = __halves2half2(h0, h1);
    *(__half2*)(hi + i + 2) = __halves2half2(h2, h3);
    *(__half2*)(lo + i)     = __halves2half2(l0, l1);
    *(__half2*)(lo + i + 2) = __halves2half2(l2, l3);
}

// ---------------------------------------------------------------------------
// fp32 [R,C] -> transposed, scaled fp16 hi/lo [C,R]
// ---------------------------------------------------------------------------
__global__ __launch_bounds__(256)
void transpose_split(const float* __restrict__ in, __half* __restrict__ hiT,
                     __half* __restrict__ loT, int R, int C, float scale)
{
    __shared__ float t[32][33];
    const int r0 = blockIdx.y * 32, c0 = blockIdx.x * 32;
    const int tx = threadIdx.x & 31, ty = threadIdx.x >> 5;
#pragma unroll
    for (int i = ty; i < 32; i += 8)
        t[i][tx] = in[(size_t)(r0 + i) * C + c0 + tx];
    __syncthreads();
#pragma unroll
    for (int i = ty; i < 32; i += 8) {
        float x = t[tx][i] * scale;
        __half h = __float2half_rn(x);
        __half l = __float2half_rn(x - __half2float(h));
        size_t o = (size_t)(c0 + i) * R + r0 + tx;
        hiT[o] = h; loT[o] = l;
    }
}

// fp32 [R,C] -> transposed fp16 hi only [C,R] (batched via z)
__global__ __launch_bounds__(256)
void transpose_hi(const float* __restrict__ in, __half* __restrict__ hiT,
                  int R, int C, long long sIn, long long sOut)
{
    __shared__ float t[32][33];
    in  += (size_t)blockIdx.z * sIn;
    hiT += (size_t)blockIdx.z * sOut;
    const int r0 = blockIdx.y * 32, c0 = blockIdx.x * 32;
    const int tx = threadIdx.x & 31, ty = threadIdx.x >> 5;
#pragma unroll
    for (int i = ty; i < 32; i += 8)
        t[i][tx] = in[(size_t)(r0 + i) * C + c0 + tx];
    __syncthreads();
#pragma unroll
    for (int i = ty; i < 32; i += 8)
        hiT[(size_t)(c0 + i) * R + r0 + tx] = __float2half_rn(t[tx][i]);
}

// ---------------------------------------------------------------------------
// Row softmax (4096 cols) fused with fp16 hi/lo split of the weights
// ---------------------------------------------------------------------------
__global__ __launch_bounds__(256)
void softmax_split(const float* __restrict__ S, __half* __restrict__ Ph,
                   __half* __restrict__ Pl)
{
    const size_t row = blockIdx.x;
    const float* p = S + row * (size_t)SS;
    const int tid = threadIdx.x;

    float4 v[4];
    float m = -INFINITY;
#pragma unroll
    for (int i = 0; i < 4; i++) {
        v[i] = ((const float4*)p)[tid + i * 256];
        m = fmaxf(m, fmaxf(fmaxf(v[i].x, v[i].y), fmaxf(v[i].z, v[i].w)));
    }
    __shared__ float red[256];
    red[tid] = m; __syncthreads();
#pragma unroll
    for (int s = 128; s > 0; s >>= 1) {
        if (tid < s) red[tid] = fmaxf(red[tid], red[tid + s]);
        __syncthreads();
    }
    const float rowmax = red[0];
    __syncthreads();

    float sum = 0.0f;
#pragma unroll
    for (int i = 0; i < 4; i++) {
        v[i].x = __expf(v[i].x - rowmax);
        v[i].y = __expf(v[i].y - rowmax);
        v[i].z = __expf(v[i].z - rowmax);
        v[i].w = __expf(v[i].w - rowmax);
        sum += v[i].x + v[i].y + v[i].z + v[i].w;
    }
    red[tid] = sum; __syncthreads();
#pragma unroll
    for (int s = 128; s > 0; s >>= 1) {
        if (tid < s) red[tid] += red[tid + s];
        __syncthreads();
    }
    const float inv = 1.0f / red[0];
    __syncthreads();

#pragma unroll
    for (int i = 0; i < 4; i++) {
        float f0 = v[i].x * inv, f1 = v[i].y * inv, f2 = v[i].z * inv, f3 = v[i].w * inv;
        __half h0 = __float2half_rn(f0), h1 = __float2half_rn(f1);
        __half h2 = __float2half_rn(f2), h3 = __float2half_rn(f3);
        __half l0 = __float2half_rn(f0 - __half2float(h0));
        __half l1 = __float2half_rn(f1 - __half2float(h1));
        __half l2 = __float2half_rn(f2 - __half2float(h2));
        __half l3 = __float2half_rn(f3 - __half2float(h3));
        size_t o = row * (size_t)SS + (size_t)(tid + i * 256) * 4;
        *(__half2*)(Ph + o)     = __halves2half2(h0, h1);
        *(__half2*)(Ph + o + 2) = __halves2half2(h2, h3);
        *(__half2*)(Pl + o)     = __halves2half2(l0, l1);
        *(__half2*)(Pl + o + 2) = __halves2half2(l2, l3);
    }
}

// ---------------------------------------------------------------------------
// kernel_launch — graph-capturable pipeline
// ---------------------------------------------------------------------------
extern "C" void kernel_launch(void* const* d_in, const int* in_sizes, int n_in,
                              void* d_out, int out_size)
{
    const float* X  = (const float*)d_in[0];
    const float* Wq = (const float*)d_in[1];
    const float* Wk = (const float*)d_in[2];
    const float* Wv = (const float*)d_in[3];
    float* out = (float*)d_out;

    float *Vf, *Sc;
    __half *Xhi, *Xlo, *Wh, *Wl, *Qhi, *Qlo, *Khi, *Klo, *Vthi, *Phi, *Plo;
    cudaGetSymbolAddress((void**)&Vf, g_Vf);
    cudaGetSymbolAddress((void**)&Sc, g_S);
    cudaGetSymbolAddress((void**)&Xhi, g_Xhi);
    cudaGetSymbolAddress((void**)&Xlo, g_Xlo);
    cudaGetSymbolAddress((void**)&Wh, g_Wh);
    cudaGetSymbolAddress((void**)&Wl, g_Wl);
    cudaGetSymbolAddress((void**)&Qhi, g_Qhi);
    cudaGetSymbolAddress((void**)&Qlo, g_Qlo);
    cudaGetSymbolAddress((void**)&Khi, g_Khi);
    cudaGetSymbolAddress((void**)&Klo, g_Klo);
    cudaGetSymbolAddress((void**)&Vthi, g_Vthi);
    cudaGetSymbolAddress((void**)&Phi, g_Phi);
    cudaGetSymbolAddress((void**)&Plo, g_Plo);

    const int SMEM3 = 2 * 4 * TILE_T;   // 81920 (BT=2)
    const int SMEM2 = 2 * 3 * TILE_T;   // 61440 (BT=1)
    cudaFuncSetAttribute(gemm_mma<2,false>, cudaFuncAttributeMaxDynamicSharedMemorySize, SMEM3);
    cudaFuncSetAttribute(gemm_mma<2,true>,  cudaFuncAttributeMaxDynamicSharedMemorySize, SMEM3);
    cudaFuncSetAttribute(gemm_mma<1,false>, cudaFuncAttributeMaxDynamicSharedMemorySize, SMEM2);

    const size_t WSZ = (size_t)AA * DD;
    const float WS = 16.0f, INV_WS = 1.0f / 16.0f;

    // 1) split X; transpose+split the three weight matrices (scaled by 16)
    split_plain<<<(MTOT * (size_t)DD) / 1024, 256>>>(X, Xhi, Xlo, (size_t)MTOT * DD);
    {
        dim3 g(AA / 32, DD / 32, 1);
        transpose_split<<<g, 256>>>(Wq, Wh + 0 * WSZ, Wl + 0 * WSZ, DD, AA, WS);
        transpose_split<<<g, 256>>>(Wk, Wh + 1 * WSZ, Wl + 1 * WSZ, DD, AA, WS);
        transpose_split<<<g, 256>>>(Wv, Wh + 2 * WSZ, Wl + 2 * WSZ, DD, AA, WS);
    }

    // 2) projections (3-term): Q,K -> fp16 hi/lo; V -> fp32
    {
        dim3 g(AA / 128, MTOT / 128, 1);
        gemm_mma<2,true><<<g, 256, SMEM3>>>(Xhi, Xlo, Wh + 0*WSZ, Wl + 0*WSZ,
                                            nullptr, Qhi, Qlo, DD, AA, 0, 0, 0, INV_WS);
        gemm_mma<2,true><<<g, 256, SMEM3>>>(Xhi, Xlo, Wh + 1*WSZ, Wl + 1*WSZ,
                                            nullptr, Khi, Klo, DD, AA, 0, 0, 0, INV_WS);
        gemm_mma<2,false><<<g, 256, SMEM3>>>(Xhi, Xlo, Wh + 2*WSZ, Wl + 2*WSZ,
                                             Vf, nullptr, nullptr, DD, AA, 0, 0, 0, INV_WS);
    }

    // 3) transpose V per batch to fp16 [A,S], hi only
    {
        dim3 g(AA / 32, SS / 32, BB);
        transpose_hi<<<g, 256>>>(Vf, Vthi, SS, AA,
                                 (long long)SS * AA, (long long)SS * AA);
    }

    // 4) scores (3-term): S = Q @ K^T per batch
    {
        dim3 g(SS / 128, SS / 128, BB);
        gemm_mma<2,false><<<g, 256, SMEM3>>>(Qhi, Qlo, Khi, Klo, Sc, nullptr, nullptr,
                                             AA, SS,
                                             (long long)SS * AA, (long long)SS * AA,
                                             (long long)SS * SS, 1.0f);
    }

    // 5) softmax + split to fp16 hi/lo
    softmax_split<<<BB * SS, 256>>>(Sc, Phi, Plo);

    // 6) output (2-term): O = P @ V per batch
    {
        dim3 g(AA / 128, SS / 128, BB);
        gemm_mma<1,false><<<g, 256, SMEM2>>>(Phi, Plo, Vthi, nullptr, out, nullptr, nullptr,
                                             SS, AA,
                                             (long long)SS * SS, (long long)AA * SS,
                                             (long long)SS * AA, 1.0f);
    }
}

// round 7
// speedup vs baseline: 3.4097x; 1.1514x over previous
#include <cuda_runtime.h>
#include <cuda_fp16.h>
#include <cstdint>
#include <math.h>

// Problem dims (fixed)
#define BB 4
#define SS 4096
#define DD 1024
#define AA 1024
#define MTOT (BB*SS)   // 16384

// ---------------------------------------------------------------------------
// Device scratch
// ---------------------------------------------------------------------------
__device__ float g_Vf[(size_t)MTOT * AA];                 // 64 MB
__device__ float g_S [(size_t)BB * SS * SS];              // 256 MB scores
__device__ __half g_Xhi[(size_t)MTOT * DD];
__device__ __half g_Xlo[(size_t)MTOT * DD];
__device__ __half g_Wh[3][(size_t)AA * DD];               // (16*W)^T splits [A,D]
__device__ __half g_Wl[3][(size_t)AA * DD];
__device__ __half g_Qhi[(size_t)MTOT * AA];
__device__ __half g_Qlo[(size_t)MTOT * AA];
__device__ __half g_Khi[(size_t)MTOT * AA];
__device__ __half g_Klo[(size_t)MTOT * AA];
__device__ __half g_Vthi[(size_t)BB * AA * SS];           // V^T per batch [A,S]
__device__ __half g_Phi[(size_t)BB * SS * SS];            // 128 MB

// ---------------------------------------------------------------------------
// Helpers
// ---------------------------------------------------------------------------
__device__ __forceinline__ uint32_t smem_u32(const void* p) {
    uint32_t a;
    asm("{ .reg .u64 t; cvta.to.shared.u64 t, %1; cvt.u32.u64 %0, t; }" : "=r"(a) : "l"(p));
    return a;
}

#define CP_ASYNC16(saddr, gaddr) \
    asm volatile("cp.async.cg.shared.global [%0], [%1], 16;" :: "r"(saddr), "l"(gaddr))
#define CP_COMMIT()  asm volatile("cp.async.commit_group;" ::: "memory")
#define CP_WAIT1()   asm volatile("cp.async.wait_group 1;" ::: "memory")
#define CP_WAIT0()   asm volatile("cp.async.wait_group 0;" ::: "memory")

#define MMA_F16(c, a, b) \
    asm volatile("mma.sync.aligned.m16n8k16.row.col.f32.f16.f16.f32 " \
        "{%0,%1,%2,%3}, {%4,%5,%6,%7}, {%8,%9}, {%0,%1,%2,%3};" \
        : "+f"((c)[0]), "+f"((c)[1]), "+f"((c)[2]), "+f"((c)[3]) \
        : "r"((a)[0]), "r"((a)[1]), "r"((a)[2]), "r"((a)[3]), \
          "r"((b)[0]), "r"((b)[1]))

// ---------------------------------------------------------------------------
// HMMA GEMM, fp16 hi/lo split, term count NT:
//   NT=3: AhBh + AlBh + AhBl   (A split, B split)
//   NT=2: AhBh + AlBh          (A split, B hi only)
//   NT=1: AhBh                 (A hi, B hi)
// C[M,N] = A[M,K] * B[N,K]^T, K-major. CTA tile 128x128, KC=32,
// 2-stage cp.async double buffer, 2 CTAs/SM.
// 8 warps as 4(m) x 2(n); warp tile 32x64 = 2 m16 x 8 n8 mma tiles.
// ---------------------------------------------------------------------------
#define KC    32
#define ROWB  80                              // 32 fp16 (64B) + 16B pad
#define TILE_T (128 * ROWB)                   // 10240 B

__device__ __forceinline__ void load_tile32(const __half* __restrict__ g,
                                            int ldK, char* sb, int tid)
{
#pragma unroll
    for (int i = 0; i < 2; i++) {
        int ch = tid + i * 256;               // 0..511
        int row = ch >> 2, c = ch & 3;
        CP_ASYNC16(smem_u32(sb + row * ROWB + c * 16),
                   g + (size_t)row * ldK + c * 8);
    }
}

template <int NT>
__device__ __forceinline__ void load_stage(const __half* pAh, const __half* pAl,
                                           const __half* pBh, const __half* pBl,
                                           int k0, int K, char* sp, int tid)
{
    load_tile32(pAh + k0, K, sp, tid);
    if (NT >= 2) {
        load_tile32(pAl + k0, K, sp + TILE_T,     tid);
        load_tile32(pBh + k0, K, sp + 2 * TILE_T, tid);
        if (NT == 3)
            load_tile32(pBl + k0, K, sp + 3 * TILE_T, tid);
    } else {
        load_tile32(pBh + k0, K, sp + TILE_T, tid);
    }
    CP_COMMIT();
}

template <int NT, bool SPLIT_OUT>
__global__ __launch_bounds__(256, 2)
void gemm_mma(const __half* __restrict__ Ahi, const __half* __restrict__ Alo,
              const __half* __restrict__ Bhi, const __half* __restrict__ Blo,
              float* __restrict__ C,
              __half* __restrict__ Chi, __half* __restrict__ Clo,
              int K, int ldC,
              long long sA, long long sB, long long sC, float oscale)
{
    constexpr int STG = (NT + 1) * TILE_T;
    extern __shared__ __align__(128) char smem[];
    const int tid = threadIdx.x;
    const int wid = tid >> 5, lane = tid & 31;
    const int wm = wid & 3, wn = wid >> 2;    // 4(m) x 2(n)
    const int m0 = blockIdx.y * 128;
    const int n0 = blockIdx.x * 128;

    const __half* pAh = Ahi + (size_t)blockIdx.z * sA + (size_t)m0 * K;
    const __half* pAl = (NT >= 2) ? Alo + (size_t)blockIdx.z * sA + (size_t)m0 * K : nullptr;
    const __half* pBh = Bhi + (size_t)blockIdx.z * sB + (size_t)n0 * K;
    const __half* pBl = (NT == 3) ? Blo + (size_t)blockIdx.z * sB + (size_t)n0 * K : nullptr;

    float acc[2][8][4];
#pragma unroll
    for (int mt = 0; mt < 2; mt++)
#pragma unroll
        for (int nt = 0; nt < 8; nt++)
#pragma unroll
            for (int j = 0; j < 4; j++) acc[mt][nt][j] = 0.0f;

    const int nch = K >> 5;

    load_stage<NT>(pAh, pAl, pBh, pBl, 0,  K, smem,       tid);
    load_stage<NT>(pAh, pAl, pBh, pBl, KC, K, smem + STG, tid);

    const int r  = lane >> 2;        // 0..7
    const int kq = lane & 3;         // 0..3

    for (int c = 0; c < nch; ++c) {
        if (c + 1 < nch) CP_WAIT1(); else CP_WAIT0();
        __syncthreads();

        const char* sp  = smem + (c & 1) * STG;
        const char* sAh = sp;
        const char* sAl = sp + TILE_T;                       // NT>=2
        const char* sBh = sp + (NT >= 2 ? 2 : 1) * TILE_T;
        const char* sBl = sp + 3 * TILE_T;                   // NT==3

#pragma unroll
        for (int ks = 0; ks < 2; ++ks) {
            const int kb = ks * 32 + kq * 4;

            uint32_t ah[2][4], al[2][4];
#pragma unroll
            for (int mt = 0; mt < 2; mt++) {
                const int row = wm * 32 + mt * 16 + r;
                const char* a0 = sAh + row * ROWB + kb;
                const char* a1 = sAh + (row + 8) * ROWB + kb;
                ah[mt][0] = *(const uint32_t*)(a0);
                ah[mt][1] = *(const uint32_t*)(a1);
                ah[mt][2] = *(const uint32_t*)(a0 + 16);
                ah[mt][3] = *(const uint32_t*)(a1 + 16);
                if (NT >= 2) {
                    const char* b0 = sAl + row * ROWB + kb;
                    const char* b1 = sAl + (row + 8) * ROWB + kb;
                    al[mt][0] = *(const uint32_t*)(b0);
                    al[mt][1] = *(const uint32_t*)(b1);
                    al[mt][2] = *(const uint32_t*)(b0 + 16);
                    al[mt][3] = *(const uint32_t*)(b1 + 16);
                }
            }
#pragma unroll
            for (int nt = 0; nt < 8; nt++) {
                const int n = wn * 64 + nt * 8 + r;
                uint32_t bh[2];
                const char* p = sBh + n * ROWB + kb;
                bh[0] = *(const uint32_t*)(p);
                bh[1] = *(const uint32_t*)(p + 16);
#pragma unroll
                for (int mt = 0; mt < 2; mt++) {
                    MMA_F16(acc[mt][nt], ah[mt], bh);
                    if (NT >= 2) MMA_F16(acc[mt][nt], al[mt], bh);
                }
                if (NT == 3) {
                    uint32_t bl[2];
                    const char* q = sBl + n * ROWB + kb;
                    bl[0] = *(const uint32_t*)(q);
                    bl[1] = *(const uint32_t*)(q + 16);
#pragma unroll
                    for (int mt = 0; mt < 2; mt++)
                        MMA_F16(acc[mt][nt], ah[mt], bl);
                }
            }
        }

        if (c + 2 < nch) {
            __syncthreads();
            load_stage<NT>(pAh, pAl, pBh, pBl, (c + 2) * KC, K,
                           smem + (c & 1) * STG, tid);
        }
    }

    // epilogue
    const int cq = (lane & 3) * 2;
    if (!SPLIT_OUT) {
        float* Cw = C + (size_t)blockIdx.z * sC
                      + (size_t)(m0 + wm * 32) * ldC + n0 + wn * 64;
#pragma unroll
        for (int mt = 0; mt < 2; mt++)
#pragma unroll
            for (int nt = 0; nt < 8; nt++) {
                float* p0 = Cw + (size_t)(mt * 16 + r) * ldC + nt * 8 + cq;
                float* p1 = p0 + 8 * (size_t)ldC;
                *(float2*)p0 = make_float2(acc[mt][nt][0] * oscale, acc[mt][nt][1] * oscale);
                *(float2*)p1 = make_float2(acc[mt][nt][2] * oscale, acc[mt][nt][3] * oscale);
            }
    } else {
        const size_t off = (size_t)blockIdx.z * sC
                         + (size_t)(m0 + wm * 32) * ldC + n0 + wn * 64;
        __half* Hw = Chi + off;
        __half* Lw = Clo + off;
#pragma unroll
        for (int mt = 0; mt < 2; mt++)
#pragma unroll
            for (int nt = 0; nt < 8; nt++) {
                const size_t o0 = (size_t)(mt * 16 + r) * ldC + nt * 8 + cq;
                const size_t o1 = o0 + 8 * (size_t)ldC;
                float x0 = acc[mt][nt][0] * oscale, x1 = acc[mt][nt][1] * oscale;
                float x2 = acc[mt][nt][2] * oscale, x3 = acc[mt][nt][3] * oscale;
                __half h0 = __float2half_rn(x0), h1 = __float2half_rn(x1);
                __half h2 = __float2half_rn(x2), h3 = __float2half_rn(x3);
                *(__half2*)(Hw + o0) = __halves2half2(h0, h1);
                *(__half2*)(Hw + o1) = __halves2half2(h2, h3);
                __half l0 = __float2half_rn(x0 - __half2float(h0));
                __half l1 = __float2half_rn(x1 - __half2float(h1));
                __half l2 = __float2half_rn(x2 - __half2float(h2));
                __half l3 = __float2half_rn(x3 - __half2float(h3));
                *(__half2*)(Lw + o0) = __halves2half2(l0, l1);
                *(__half2*)(Lw + o1) = __halves2half2(l2, l3);
            }
    }
}

// ---------------------------------------------------------------------------
// fp32 -> fp16 hi/lo split (elementwise)
// ---------------------------------------------------------------------------
__global__ __launch_bounds__(256)
void split_plain(const float* __restrict__ in, __half* __restrict__ hi,
                 __half* __restrict__ lo, size_t n)
{
    size_t i = ((size_t)blockIdx.x * 256 + threadIdx.x) * 4;
    if (i >= n) return;
    float4 x = *(const float4*)(in + i);
    __half h0 = __float2half_rn(x.x), h1 = __float2half_rn(x.y);
    __half h2 = __float2half_rn(x.z), h3 = __float2half_rn(x.w);
    __half l0 = __float2half_rn(x.x - __half2float(h0));
    __half l1 = __float2half_rn(x.y - __half2float(h1));
    __half l2 = __float2half_rn(x.z - __half2float(h2));
    __half l3 = __float2half_rn(x.w - __half2float(h3));
    *(__half2*)(hi + i)     = __halves2half2(h0, h1);
    *(__half2*)(hi + i + 2) = __halves2half2(h2, h3);
    *(__half2*)(lo + i)     = __halves2half2(l0, l1);
    *(__half2*)(lo + i + 2) = __halves2half2(l2, l3);
}

// ---------------------------------------------------------------------------
// fp32 [R,C] -> transposed, scaled fp16 hi/lo [C,R]
// ---------------------------------------------------------------------------
__global__ __launch_bounds__(256)
void transpose_split(const float* __restrict__ in, __half* __restrict__ hiT,
                     __half* __restrict__ loT, int R, int C, float scale)
{
    __shared__ float t[32][33];
    const int r0 = blockIdx.y * 32, c0 = blockIdx.x * 32;
    const int tx = threadIdx.x & 31, ty = threadIdx.x >> 5;
#pragma unroll
    for (int i = ty; i < 32; i += 8)
        t[i][tx] = in[(size_t)(r0 + i) * C + c0 + tx];
    __syncthreads();
#pragma unroll
    for (int i = ty; i < 32; i += 8) {
        float x = t[tx][i] * scale;
        __half h = __float2half_rn(x);
        __half l = __float2half_rn(x - __half2float(h));
        size_t o = (size_t)(c0 + i) * R + r0 + tx;
        hiT[o] = h; loT[o] = l;
    }
}

// fp32 [R,C] -> transposed fp16 hi only [C,R] (batched via z)
__global__ __launch_bounds__(256)
void transpose_hi(const float* __restrict__ in, __half* __restrict__ hiT,
                  int R, int C, long long sIn, long long sOut)
{
    __shared__ float t[32][33];
    in  += (size_t)blockIdx.z * sIn;
    hiT += (size_t)blockIdx.z * sOut;
    const int r0 = blockIdx.y * 32, c0 = blockIdx.x * 32;
    const int tx = threadIdx.x & 31, ty = threadIdx.x >> 5;
#pragma unroll
    for (int i = ty; i < 32; i += 8)
        t[i][tx] = in[(size_t)(r0 + i) * C + c0 + tx];
    __syncthreads();
#pragma unroll
    for (int i = ty; i < 32; i += 8)
        hiT[(size_t)(c0 + i) * R + r0 + tx] = __float2half_rn(t[tx][i]);
}

// ---------------------------------------------------------------------------
// Row softmax (4096 cols), write fp16 (hi only)
// ---------------------------------------------------------------------------
__global__ __launch_bounds__(256)
void softmax_f16(const float* __restrict__ S, __half* __restrict__ Ph)
{
    const size_t row = blockIdx.x;
    const float* p = S + row * (size_t)SS;
    const int tid = threadIdx.x;

    float4 v[4];
    float m = -INFINITY;
#pragma unroll
    for (int i = 0; i < 4; i++) {
        v[i] = ((const float4*)p)[tid + i * 256];
        m = fmaxf(m, fmaxf(fmaxf(v[i].x, v[i].y), fmaxf(v[i].z, v[i].w)));
    }
    __shared__ float red[256];
    red[tid] = m; __syncthreads();
#pragma unroll
    for (int s = 128; s > 0; s >>= 1) {
        if (tid < s) red[tid] = fmaxf(red[tid], red[tid + s]);
        __syncthreads();
    }
    const float rowmax = red[0];
    __syncthreads();

    float sum = 0.0f;
#pragma unroll
    for (int i = 0; i < 4; i++) {
        v[i].x = __expf(v[i].x - rowmax);
        v[i].y = __expf(v[i].y - rowmax);
        v[i].z = __expf(v[i].z - rowmax);
        v[i].w = __expf(v[i].w - rowmax);
        sum += v[i].x + v[i].y + v[i].z + v[i].w;
    }
    red[tid] = sum; __syncthreads();
#pragma unroll
    for (int s = 128; s > 0; s >>= 1) {
        if (tid < s) red[tid] += red[tid + s];
        __syncthreads();
    }
    const float inv = 1.0f / red[0];
    __syncthreads();

#pragma unroll
    for (int i = 0; i < 4; i++) {
        size_t o = row * (size_t)SS + (size_t)(tid + i * 256) * 4;
        *(__half2*)(Ph + o)     = __halves2half2(__float2half_rn(v[i].x * inv),
                                                 __float2half_rn(v[i].y * inv));
        *(__half2*)(Ph + o + 2) = __halves2half2(__float2half_rn(v[i].z * inv),
                                                 __float2half_rn(v[i].w * inv));
    }
}

// ---------------------------------------------------------------------------
// kernel_launch — graph-capturable pipeline
// ---------------------------------------------------------------------------
extern "C" void kernel_launch(void* const* d_in, const int* in_sizes, int n_in,
                              void* d_out, int out_size)
{
    const float* X  = (const float*)d_in[0];
    const float* Wq = (const float*)d_in[1];
    const float* Wk = (const float*)d_in[2];
    const float* Wv = (const float*)d_in[3];
    float* out = (float*)d_out;

    float *Vf, *Sc;
    __half *Xhi, *Xlo, *Wh, *Wl, *Qhi, *Qlo, *Khi, *Klo, *Vthi, *Phi;
    cudaGetSymbolAddress((void**)&Vf, g_Vf);
    cudaGetSymbolAddress((void**)&Sc, g_S);
    cudaGetSymbolAddress((void**)&Xhi, g_Xhi);
    cudaGetSymbolAddress((void**)&Xlo, g_Xlo);
    cudaGetSymbolAddress((void**)&Wh, g_Wh);
    cudaGetSymbolAddress((void**)&Wl, g_Wl);
    cudaGetSymbolAddress((void**)&Qhi, g_Qhi);
    cudaGetSymbolAddress((void**)&Qlo, g_Qlo);
    cudaGetSymbolAddress((void**)&Khi, g_Khi);
    cudaGetSymbolAddress((void**)&Klo, g_Klo);
    cudaGetSymbolAddress((void**)&Vthi, g_Vthi);
    cudaGetSymbolAddress((void**)&Phi, g_Phi);

    const int SMEM_NT3 = 2 * 4 * TILE_T;   // 81920
    const int SMEM_NT2 = 2 * 3 * TILE_T;   // 61440
    const int SMEM_NT1 = 2 * 2 * TILE_T;   // 40960
    cudaFuncSetAttribute(gemm_mma<3,false>, cudaFuncAttributeMaxDynamicSharedMemorySize, SMEM_NT3);
    cudaFuncSetAttribute(gemm_mma<3,true>,  cudaFuncAttributeMaxDynamicSharedMemorySize, SMEM_NT3);
    cudaFuncSetAttribute(gemm_mma<2,false>, cudaFuncAttributeMaxDynamicSharedMemorySize, SMEM_NT2);
    cudaFuncSetAttribute(gemm_mma<1,false>, cudaFuncAttributeMaxDynamicSharedMemorySize, SMEM_NT1);

    const size_t WSZ = (size_t)AA * DD;
    const float WS = 16.0f, INV_WS = 1.0f / 16.0f;

    // 1) split X; transpose+split the three weight matrices (scaled by 16)
    split_plain<<<(MTOT * (size_t)DD) / 1024, 256>>>(X, Xhi, Xlo, (size_t)MTOT * DD);
    {
        dim3 g(AA / 32, DD / 32, 1);
        transpose_split<<<g, 256>>>(Wq, Wh + 0 * WSZ, Wl + 0 * WSZ, DD, AA, WS);
        transpose_split<<<g, 256>>>(Wk, Wh + 1 * WSZ, Wl + 1 * WSZ, DD, AA, WS);
        transpose_split<<<g, 256>>>(Wv, Wh + 2 * WSZ, Wl + 2 * WSZ, DD, AA, WS);
    }

    // 2) projections: Q,K 3-term -> fp16 hi/lo; V 2-term -> fp32
    {
        dim3 g(AA / 128, MTOT / 128, 1);
        gemm_mma<3,true><<<g, 256, SMEM_NT3>>>(Xhi, Xlo, Wh + 0*WSZ, Wl + 0*WSZ,
                                               nullptr, Qhi, Qlo, DD, AA, 0, 0, 0, INV_WS);
        gemm_mma<3,true><<<g, 256, SMEM_NT3>>>(Xhi, Xlo, Wh + 1*WSZ, Wl + 1*WSZ,
                                               nullptr, Khi, Klo, DD, AA, 0, 0, 0, INV_WS);
        gemm_mma<2,false><<<g, 256, SMEM_NT2>>>(Xhi, Xlo, Wh + 2*WSZ, nullptr,
                                                Vf, nullptr, nullptr, DD, AA, 0, 0, 0, INV_WS);
    }

    // 3) transpose V per batch to fp16 [A,S], hi only
    {
        dim3 g(AA / 32, SS / 32, BB);
        transpose_hi<<<g, 256>>>(Vf, Vthi, SS, AA,
                                 (long long)SS * AA, (long long)SS * AA);
    }

    // 4) scores (3-term): S = Q @ K^T per batch
    {
        dim3 g(SS / 128, SS / 128, BB);
        gemm_mma<3,false><<<g, 256, SMEM_NT3>>>(Qhi, Qlo, Khi, Klo, Sc, nullptr, nullptr,
                                                AA, SS,
                                                (long long)SS * AA, (long long)SS * AA,
                                                (long long)SS * SS, 1.0f);
    }

    // 5) softmax -> fp16 P (hi only)
    softmax_f16<<<BB * SS, 256>>>(Sc, Phi);

    // 6) output (1-term): O = P @ V per batch
    {
        dim3 g(AA / 128, SS / 128, BB);
        gemm_mma<1,false><<<g, 256, SMEM_NT1>>>(Phi, nullptr, Vthi, nullptr, out, nullptr, nullptr,
                                                SS, AA,
                                                (long long)SS * SS, (long long)AA * SS,
                                                (long long)SS * AA, 1.0f);
    }
}